// round 9
// baseline (speedup 1.0000x reference)
#include <cuda_runtime.h>
#include <cuda_bf16.h>
#include <cstdint>
#include <cstddef>

#define BQ 2
#define QL 1024
#define ML 1024
#define KL 2048
#define DM 1024
#define NH 16
#define DH 64

// ---------------- scratch (device globals: allocation-free) ----------------
__device__ float g_bd[(size_t)32 * 1024 * 2048];    // BD (pre-shifted) [B*H, Q, K]

__device__ __nv_bfloat16 g_ah[(size_t)4096 * 1024], g_al[(size_t)4096 * 1024];
__device__ __nv_bfloat16 g_rh[(size_t)4096 * 1024], g_rl[(size_t)4096 * 1024];
__device__ __nv_bfloat16 g_oh[(size_t)2048 * 1024], g_ol[(size_t)2048 * 1024];
__device__ __nv_bfloat16 g_wqh[(size_t)3072 * 1024], g_wql[(size_t)3072 * 1024];
__device__ __nv_bfloat16 g_wrh[(size_t)1024 * 1024], g_wrl[(size_t)1024 * 1024];
__device__ __nv_bfloat16 g_woh[(size_t)1024 * 1024], g_wol[(size_t)1024 * 1024];

__device__ __nv_bfloat16 g_quh[(size_t)32 * 1024 * 64], g_qul[(size_t)32 * 1024 * 64];
__device__ __nv_bfloat16 g_qvh[(size_t)32 * 1024 * 64], g_qvl[(size_t)32 * 1024 * 64];
__device__ __nv_bfloat16 g_khh[(size_t)32 * 2048 * 64], g_khl[(size_t)32 * 2048 * 64];
__device__ __nv_bfloat16 g_rrh[(size_t)32 * 2048 * 64], g_rrl[(size_t)32 * 2048 * 64];
__device__ __nv_bfloat16 g_vjh[(size_t)32 * 2048 * 64], g_vjl[(size_t)32 * 2048 * 64];

// ======================= helpers ===========================================
__device__ __forceinline__ uint32_t smem_u32(const void* p) {
    uint32_t a;
    asm("{ .reg .u64 t; cvta.to.shared.u64 t, %1; cvt.u32.u64 %0, t; }"
        : "=r"(a) : "l"(p));
    return a;
}
__device__ __forceinline__ void split1(float x, __nv_bfloat16& h, __nv_bfloat16& l) {
    h = __float2bfloat16_rn(x);
    l = __float2bfloat16_rn(x - __bfloat162float(h));
}
__device__ __forceinline__ uint32_t pack2(__nv_bfloat16 a, __nv_bfloat16 b) {
    __nv_bfloat162 v = make_bfloat162(a, b);
    return *(uint32_t*)&v;
}
__device__ __forceinline__ void ldmx4(uint32_t a[4], uint32_t addr) {
    asm volatile("ldmatrix.sync.aligned.m8n8.x4.shared.b16 {%0,%1,%2,%3}, [%4];"
        : "=r"(a[0]), "=r"(a[1]), "=r"(a[2]), "=r"(a[3]) : "r"(addr));
}
__device__ __forceinline__ void ldmx4t(uint32_t a[4], uint32_t addr) {
    asm volatile("ldmatrix.sync.aligned.m8n8.x4.trans.shared.b16 {%0,%1,%2,%3}, [%4];"
        : "=r"(a[0]), "=r"(a[1]), "=r"(a[2]), "=r"(a[3]) : "r"(addr));
}
__device__ __forceinline__ void mma16816(float c[4], const uint32_t a[4], const uint32_t b[2]) {
    asm volatile("mma.sync.aligned.m16n8k16.row.col.f32.bf16.bf16.f32 "
        "{%0,%1,%2,%3}, {%4,%5,%6,%7}, {%8,%9}, {%0,%1,%2,%3};"
        : "+f"(c[0]), "+f"(c[1]), "+f"(c[2]), "+f"(c[3])
        : "r"(a[0]), "r"(a[1]), "r"(a[2]), "r"(a[3]), "r"(b[0]), "r"(b[1]));
}
#define CP16(dst, src) \
    asm volatile("cp.async.cg.shared.global [%0], [%1], 16;" :: "r"(dst), "l"(src) : "memory")
#define CP_COMMIT() asm volatile("cp.async.commit_group;" ::: "memory")
#define CP_WAIT(n)  asm volatile("cp.async.wait_group %0;" :: "n"(n) : "memory")

// ===================== prep: split kernels ==================================
__global__ __launch_bounds__(256)
void split_concat(const float* __restrict__ mem, const float* __restrict__ inp,
                  __nv_bfloat16* __restrict__ hi, __nv_bfloat16* __restrict__ lo)
{
    size_t idx = ((size_t)blockIdx.x * 256 + threadIdx.x) * 4;
    size_t row = idx >> 10;
    int col = (int)(idx & 1023);
    int b = (int)(row >> 11);
    int k = (int)(row & 2047);
    const float* src = (k < ML) ? mem + ((size_t)(b * ML + k) << 10)
                                : inp + ((size_t)(b * QL + (k - ML)) << 10);
    float4 v = *(const float4*)(src + col);
    __nv_bfloat16 h0, h1, h2, h3, l0, l1, l2, l3;
    split1(v.x, h0, l0); split1(v.y, h1, l1);
    split1(v.z, h2, l2); split1(v.w, h3, l3);
    __nv_bfloat162* H = (__nv_bfloat162*)(hi + idx);
    __nv_bfloat162* L = (__nv_bfloat162*)(lo + idx);
    H[0] = make_bfloat162(h0, h1); H[1] = make_bfloat162(h2, h3);
    L[0] = make_bfloat162(l0, l1); L[1] = make_bfloat162(l2, l3);
}

__global__ __launch_bounds__(256)
void split_plain(const float* __restrict__ src,
                 __nv_bfloat16* __restrict__ hi, __nv_bfloat16* __restrict__ lo)
{
    size_t idx = ((size_t)blockIdx.x * 256 + threadIdx.x) * 4;
    float4 v = *(const float4*)(src + idx);
    __nv_bfloat16 h0, h1, h2, h3, l0, l1, l2, l3;
    split1(v.x, h0, l0); split1(v.y, h1, l1);
    split1(v.z, h2, l2); split1(v.w, h3, l3);
    __nv_bfloat162* H = (__nv_bfloat162*)(hi + idx);
    __nv_bfloat162* L = (__nv_bfloat162*)(lo + idx);
    H[0] = make_bfloat162(h0, h1); H[1] = make_bfloat162(h2, h3);
    L[0] = make_bfloat162(l0, l1); L[1] = make_bfloat162(l2, l3);
}

__global__ __launch_bounds__(256)
void split_transpose(const float* __restrict__ in,
                     __nv_bfloat16* __restrict__ hi, __nv_bfloat16* __restrict__ lo, int N)
{
    __shared__ float s[32][33];
    const int nx = blockIdx.x * 32;
    const int ky = blockIdx.y * 32;
    const int tx = threadIdx.x & 31;
    const int ty = threadIdx.x >> 5;
#pragma unroll
    for (int r = 0; r < 32; r += 8)
        s[ty + r][tx] = in[(size_t)(ky + ty + r) * N + nx + tx];
    __syncthreads();
#pragma unroll
    for (int r = 0; r < 32; r += 8) {
        float x = s[tx][ty + r];
        __nv_bfloat16 h, l;
        split1(x, h, l);
        size_t o = (size_t)(nx + ty + r) * DM + ky + tx;
        hi[o] = h;
        lo[o] = l;
    }
}

// ============== dense GEMM: mma.sync bf16 3-term split ======================
// MODE 0: fp32 C out.  MODE 1: qkv epilogue -> per-head operands.  MODE 2: rr.
// Tile 128 x NT, BK=32, 3-stage cp.async, 8 warps (2m x 4n), x4 B pair loads.
template<int MODE>
__device__ __forceinline__ void store_opnd(int m, int n, float x0, float x1,
                                           const float* __restrict__ u,
                                           const float* __restrict__ v)
{
    int b = m >> 11, tok = m & 2047;
    __nv_bfloat16 h0, l0, h1, l1;
    if (MODE == 2) {
        int h = n >> 6, d = n & 63;
        size_t o = ((size_t)(b * NH + h) * KL + tok) * DH + d;
        split1(x0, h0, l0); split1(x1, h1, l1);
        *(uint32_t*)(g_rrh + o) = pack2(h0, h1);
        *(uint32_t*)(g_rrl + o) = pack2(l0, l1);
    } else if (n < 1024) {
        int h = n >> 6, d = n & 63, i = tok - ML;
        size_t o = ((size_t)(b * NH + h) * QL + i) * DH + d;
        split1(x0 + u[n], h0, l0); split1(x1 + u[n + 1], h1, l1);
        *(uint32_t*)(g_quh + o) = pack2(h0, h1);
        *(uint32_t*)(g_qul + o) = pack2(l0, l1);
        split1(x0 + v[n], h0, l0); split1(x1 + v[n + 1], h1, l1);
        *(uint32_t*)(g_qvh + o) = pack2(h0, h1);
        *(uint32_t*)(g_qvl + o) = pack2(l0, l1);
    } else if (n < 2048) {
        int h = (n - 1024) >> 6, d = n & 63;
        size_t o = ((size_t)(b * NH + h) * KL + tok) * DH + d;
        split1(x0, h0, l0); split1(x1, h1, l1);
        *(uint32_t*)(g_vjh + o) = pack2(h0, h1);
        *(uint32_t*)(g_vjl + o) = pack2(l0, l1);
    } else {
        int h = (n - 2048) >> 6, d = n & 63;
        size_t o = ((size_t)(b * NH + h) * KL + tok) * DH + d;
        split1(x0, h0, l0); split1(x1, h1, l1);
        *(uint32_t*)(g_khh + o) = pack2(h0, h1);
        *(uint32_t*)(g_khl + o) = pack2(l0, l1);
    }
}

template<int MODE, int NT>
__global__ __launch_bounds__(256, 1)
void gemm_bf3(const __nv_bfloat16* __restrict__ Ah, const __nv_bfloat16* __restrict__ Al,
              const __nv_bfloat16* __restrict__ Bh, const __nv_bfloat16* __restrict__ Bl,
              const float* __restrict__ bias, float* __restrict__ C, int N,
              const float* __restrict__ u, const float* __restrict__ v)
{
    constexpr int JN = NT / 32;              // B fragments per warp (warp_n span NT/4)
    constexpr uint32_t AB = 128 * 80;        // one A array bytes
    constexpr uint32_t BB = (uint32_t)NT * 80;
    constexpr uint32_t STG = 2 * AB + 2 * BB;
    constexpr int TC = 1024 + 8 * NT;        // 16B chunks per stage
    constexpr int REPS = TC / 256;
    constexpr int BSH = (NT == 256) ? 10 : 9;

    extern __shared__ char sm[];
    const uint32_t sb = smem_u32(sm);
    const int t = threadIdx.x;
    const int lane = t & 31;
    const int wid = t >> 5;
    const int m0 = blockIdx.y * 128;
    const int n0 = blockIdx.x * NT;
    if (MODE == 1 && n0 + NT <= 1024 && ((m0 & 2047) + 128) <= ML) return;

    const int warp_m = (wid & 1) * 64;
    const int warp_n = (wid >> 1) * (NT / 4);

    const __nv_bfloat16* srcs[4] = {
        Ah + (size_t)m0 * DM, Al + (size_t)m0 * DM,
        Bh + (size_t)n0 * DM, Bl + (size_t)n0 * DM
    };

    auto issue_stage = [&](int c) {
        uint32_t dst0 = sb + (uint32_t)(c % 3) * STG;
#pragma unroll
        for (int rep = 0; rep < REPS; ++rep) {
            int ci = t + rep * 256;
            uint32_t dst;
            const __nv_bfloat16* src;
            if (ci < 1024) {
                int arr = ci >> 9;              // 0 Ah, 1 Al
                int row = (ci >> 2) & 127;
                int kc = ci & 3;
                dst = dst0 + (uint32_t)arr * AB + row * 80 + kc * 16;
                src = srcs[arr] + (size_t)row * DM + c * 32 + kc * 8;
            } else {
                int cj = ci - 1024;
                int arr = cj >> BSH;            // 0 Bh, 1 Bl
                int row = (cj >> 2) & (NT - 1);
                int kc = cj & 3;
                dst = dst0 + 2 * AB + (uint32_t)arr * BB + row * 80 + kc * 16;
                src = srcs[2 + arr] + (size_t)row * DM + c * 32 + kc * 8;
            }
            CP16(dst, src);
        }
    };

    float acc[4][JN][4];
#pragma unroll
    for (int im = 0; im < 4; ++im)
#pragma unroll
        for (int jn = 0; jn < JN; ++jn)
#pragma unroll
            for (int q = 0; q < 4; ++q) acc[im][jn][q] = 0.f;

    issue_stage(0); CP_COMMIT();
    issue_stage(1); CP_COMMIT();

    const int mrow = lane & 15;
    const int khalf = lane >> 4;
    const int brow = (lane & 7);
    const int bkh = (lane >> 3) & 1;
    const int bpair = lane >> 4;              // which matrix pair for x4 B

    const int NCH = DM / 32;
    for (int c = 0; c < NCH; ++c) {
        CP_WAIT(1);
        __syncthreads();
        if (c + 2 < NCH) issue_stage(c + 2);
        CP_COMMIT();

        const uint32_t st = sb + (uint32_t)(c % 3) * STG;
#pragma unroll
        for (int kk = 0; kk < 32; kk += 16) {
            uint32_t ah[4][4], al[4][4];
#pragma unroll
            for (int im = 0; im < 4; ++im) {
                uint32_t aaddr = st + (warp_m + im * 16 + mrow) * 80 + (kk + khalf * 8) * 2;
                ldmx4(ah[im], aaddr);
                ldmx4(al[im], aaddr + AB);
            }
#pragma unroll
            for (int j2 = 0; j2 < JN / 2; ++j2) {
                uint32_t baddr = st + 2 * AB
                    + (warp_n + (j2 * 2 + bpair) * 8 + brow) * 80 + (kk + bkh * 8) * 2;
                uint32_t b4h[4], b4l[4];
                ldmx4(b4h, baddr);
                ldmx4(b4l, baddr + BB);
#pragma unroll
                for (int im = 0; im < 4; ++im) {
                    mma16816(acc[im][2 * j2],     ah[im], &b4h[0]);
                    mma16816(acc[im][2 * j2],     ah[im], &b4l[0]);
                    mma16816(acc[im][2 * j2],     al[im], &b4h[0]);
                    mma16816(acc[im][2 * j2 + 1], ah[im], &b4h[2]);
                    mma16816(acc[im][2 * j2 + 1], ah[im], &b4l[2]);
                    mma16816(acc[im][2 * j2 + 1], al[im], &b4h[2]);
                }
            }
        }
    }

    if (MODE == 0) {
#pragma unroll
        for (int im = 0; im < 4; ++im) {
            int m = m0 + warp_m + im * 16 + (lane >> 2);
#pragma unroll
            for (int jn = 0; jn < JN; ++jn) {
                int n = n0 + warp_n + jn * 8 + (lane & 3) * 2;
                float b0 = bias[n], b1 = bias[n + 1];
                float2 v0, v1;
                v0.x = acc[im][jn][0] + b0; v0.y = acc[im][jn][1] + b1;
                v1.x = acc[im][jn][2] + b0; v1.y = acc[im][jn][3] + b1;
                *(float2*)(C + (size_t)m * N + n) = v0;
                *(float2*)(C + (size_t)(m + 8) * N + n) = v1;
            }
        }
    } else {
#pragma unroll
        for (int im = 0; im < 4; ++im) {
            int m = m0 + warp_m + im * 16 + (lane >> 2);
#pragma unroll
            for (int jn = 0; jn < JN; ++jn) {
                int n = n0 + warp_n + jn * 8 + (lane & 3) * 2;
                float b0 = bias[n], b1 = bias[n + 1];
                store_opnd<MODE>(m, n, acc[im][jn][0] + b0, acc[im][jn][1] + b1, u, v);
                store_opnd<MODE>(m + 8, n, acc[im][jn][2] + b0, acc[im][jn][3] + b1, u, v);
            }
        }
    }
}

// ============== BD score GEMM (mma, K=64, pre-shifted scatter) ==============
#define SRS 144
#define SARRB (128 * SRS)
#define SCORE_SMEM (4 * SARRB)

__global__ __launch_bounds__(256, 1)
void bd_mma()
{
    const int bh = blockIdx.z;
    const int i0 = blockIdx.y * 128;
    const int p0 = blockIdx.x * 128;
    if (i0 + p0 + 254 < QL - 1) return;

    extern __shared__ char sm[];
    const uint32_t sb = smem_u32(sm);
    const int t = threadIdx.x;
    const int lane = t & 31;
    const int wid = t >> 5;
    const int warp_m = (wid & 1) * 64;
    const int warp_n = (wid >> 1) * 32;

    const __nv_bfloat16* srcs[4] = {
        g_qvh + ((size_t)bh * QL + i0) * DH,
        g_qvl + ((size_t)bh * QL + i0) * DH,
        g_rrh + ((size_t)bh * KL + p0) * DH,
        g_rrl + ((size_t)bh * KL + p0) * DH
    };
#pragma unroll
    for (int arr = 0; arr < 4; ++arr) {
#pragma unroll
        for (int rep = 0; rep < 4; ++rep) {
            int ci = t + rep * 256;
            int row = ci >> 3;
            int kc = ci & 7;
            uint32_t dst = sb + arr * SARRB + row * SRS + kc * 16;
            CP16(dst, srcs[arr] + (size_t)row * DH + kc * 8);
        }
    }
    CP_COMMIT();
    CP_WAIT(0);
    __syncthreads();

    float acc[4][4][4];
#pragma unroll
    for (int im = 0; im < 4; ++im)
#pragma unroll
        for (int jn = 0; jn < 4; ++jn)
#pragma unroll
            for (int q = 0; q < 4; ++q) acc[im][jn][q] = 0.f;

    const int mrow = lane & 15;
    const int khalf = lane >> 4;
    const int brow = lane & 7;
    const int bkh = (lane >> 3) & 1;
    const int bpair = lane >> 4;
#pragma unroll
    for (int kk = 0; kk < 64; kk += 16) {
        uint32_t ah[4][4], al[4][4];
#pragma unroll
        for (int im = 0; im < 4; ++im) {
            uint32_t aaddr = sb + (warp_m + im * 16 + mrow) * SRS + (kk + khalf * 8) * 2;
            ldmx4(ah[im], aaddr);
            ldmx4(al[im], aaddr + SARRB);
        }
#pragma unroll
        for (int j2 = 0; j2 < 2; ++j2) {
            uint32_t baddr = sb + 2 * SARRB
                + (warp_n + (j2 * 2 + bpair) * 8 + brow) * SRS + (kk + bkh * 8) * 2;
            uint32_t b4h[4], b4l[4];
            ldmx4(b4h, baddr);
            ldmx4(b4l, baddr + SARRB);
#pragma unroll
            for (int im = 0; im < 4; ++im) {
                mma16816(acc[im][2 * j2],     ah[im], &b4h[0]);
                mma16816(acc[im][2 * j2],     ah[im], &b4l[0]);
                mma16816(acc[im][2 * j2],     al[im], &b4h[0]);
                mma16816(acc[im][2 * j2 + 1], ah[im], &b4h[2]);
                mma16816(acc[im][2 * j2 + 1], ah[im], &b4l[2]);
                mma16816(acc[im][2 * j2 + 1], al[im], &b4h[2]);
            }
        }
    }

#pragma unroll
    for (int im = 0; im < 4; ++im) {
        int m = i0 + warp_m + im * 16 + (lane >> 2);
        float* r0 = g_bd + ((size_t)bh * QL + m) * KL;
        float* r1 = g_bd + ((size_t)bh * QL + m + 8) * KL;
        int sh0 = m - (QL - 1);
        int sh1 = m + 8 - (QL - 1);
#pragma unroll
        for (int jn = 0; jn < 4; ++jn) {
            int p = p0 + warp_n + jn * 8 + (lane & 3) * 2;
            int j0a = p + sh0;
            int j1a = p + sh1;
            if (j0a >= 0)     r0[j0a]     = acc[im][jn][0];
            if (j0a + 1 >= 0) r0[j0a + 1] = acc[im][jn][1];
            if (j1a >= 0)     r1[j1a]     = acc[im][jn][2];
            if (j1a + 1 >= 0) r1[j1a + 1] = acc[im][jn][3];
        }
    }
}

// ========== warp-autonomous flash attention: AC in-register + PV ===========
#define FCH 128
#define AQ_OFF 0u
#define AK_OFF 36864u
#define AV_OFF 110592u
#define ABUF 36864u
#define ATTN_SMEM 184320

__global__ __launch_bounds__(256, 1)
void attn_flash()
{
    extern __shared__ char sm[];
    const uint32_t sb = smem_u32(sm);
    const int bh = blockIdx.y;
    const int b = bh >> 4, h = bh & 15;
    const int i0 = (gridDim.x - 1 - blockIdx.x) * 128;
    const int t = threadIdx.x, lane = t & 31, wid = t >> 5;
    const int warp_m = wid * 16;

    const __nv_bfloat16* Kh  = g_khh + (size_t)bh * KL * DH;
    const __nv_bfloat16* Klo = g_khl + (size_t)bh * KL * DH;
    const __nv_bfloat16* Vjh = g_vjh + (size_t)bh * KL * DH;
    const __nv_bfloat16* Vjl = g_vjl + (size_t)bh * KL * DH;

    {
        const __nv_bfloat16* Qh = g_quh + ((size_t)bh * QL + i0) * DH;
        const __nv_bfloat16* Ql = g_qul + ((size_t)bh * QL + i0) * DH;
#pragma unroll
        for (int rep = 0; rep < 4; ++rep) {
            int ci = t + rep * 256;
            int row = ci >> 3, kc = ci & 7;
            uint32_t dst = sb + AQ_OFF + row * SRS + kc * 16;
            CP16(dst, Qh + (size_t)row * DH + kc * 8);
            CP16(dst + 18432u, Ql + (size_t)row * DH + kc * 8);
        }
    }
    CP_COMMIT();

    auto loadKV = [&](int c) {
        uint32_t kd = sb + AK_OFF + (uint32_t)(c & 1) * ABUF;
        uint32_t vd = sb + AV_OFF + (uint32_t)(c & 1) * ABUF;
#pragma unroll
        for (int rep = 0; rep < 4; ++rep) {
            int ci = t + rep * 256;
            int row = ci >> 3, kc = ci & 7;
            uint32_t o = row * SRS + kc * 16;
            CP16(kd + o, Kh + (size_t)(c * FCH + row) * DH + kc * 8);
            CP16(kd + o + 18432u, Klo + (size_t)(c * FCH + row) * DH + kc * 8);
            CP16(vd + o, Vjh + (size_t)(c * FCH + row) * DH + kc * 8);
            CP16(vd + o + 18432u, Vjl + (size_t)(c * FCH + row) * DH + kc * 8);
        }
    };

    const int nch = (ML + i0 + 128) / FCH;
    loadKV(0); CP_COMMIT();
    loadKV(1); CP_COMMIT();

    const int mrow = lane & 15, khalf = lane >> 4;
    const int brow = lane & 7, bkh = (lane >> 3) & 1, bpair = lane >> 4;
    const int lane16 = lane & 15;
    uint32_t aqh[4][4], aql[4][4];
    CP_WAIT(2);
    __syncthreads();
#pragma unroll
    for (int kf = 0; kf < 4; ++kf) {
        uint32_t aaddr = sb + AQ_OFF + (warp_m + mrow) * SRS + (kf * 16 + khalf * 8) * 2;
        ldmx4(aqh[kf], aaddr);
        ldmx4(aql[kf], aaddr + 18432u);
    }

    const int r0 = lane >> 2;
    const int colb = (lane & 3) * 2;
    const float* bdr0 = g_bd + ((size_t)bh * QL + i0 + warp_m + r0) * KL;
    const float* bdr1 = bdr0 + (size_t)8 * KL;
    const int lim0 = ML + i0 + warp_m + r0;
    const int lim1 = lim0 + 8;

    float pvacc[8][4];
#pragma unroll
    for (int nf = 0; nf < 8; ++nf)
#pragma unroll
        for (int q = 0; q < 4; ++q) pvacc[nf][q] = 0.f;
    float ssum0 = 0.f, ssum1 = 0.f;
    float mold0 = -1e30f, mold1 = -1e30f;

    for (int c = 0; c < nch; ++c) {
        CP_WAIT(1);
        __syncthreads();
        const uint32_t kst = sb + AK_OFF + (uint32_t)(c & 1) * ABUF;
        const uint32_t vst = sb + AV_OFF + (uint32_t)(c & 1) * ABUF;
        const int j0 = c * FCH;

        // ---- S = (q+u) . K^T  (x4 pair loads of K fragments) ----
        float S[16][4];
#pragma unroll
        for (int nf2 = 0; nf2 < 8; ++nf2) {
            S[2 * nf2][0] = S[2 * nf2][1] = S[2 * nf2][2] = S[2 * nf2][3] = 0.f;
            S[2 * nf2 + 1][0] = S[2 * nf2 + 1][1] = S[2 * nf2 + 1][2] = S[2 * nf2 + 1][3] = 0.f;
#pragma unroll
            for (int kf = 0; kf < 4; ++kf) {
                uint32_t baddr = kst + ((nf2 * 2 + bpair) * 8 + brow) * SRS
                               + (kf * 16 + bkh * 8) * 2;
                uint32_t b4h[4], b4l[4];
                ldmx4(b4h, baddr);
                ldmx4(b4l, baddr + 18432u);
                mma16816(S[2 * nf2],     aqh[kf], &b4h[0]);
                mma16816(S[2 * nf2],     aqh[kf], &b4l[0]);
                mma16816(S[2 * nf2],     aql[kf], &b4h[0]);
                mma16816(S[2 * nf2 + 1], aqh[kf], &b4h[2]);
                mma16816(S[2 * nf2 + 1], aqh[kf], &b4l[2]);
                mma16816(S[2 * nf2 + 1], aql[kf], &b4h[2]);
            }
        }

        // ---- + BD, scale, mask, row max ----
        const bool nomask = (j0 + 127) <= lim0;
        float mx0 = -1e30f, mx1 = -1e30f;
#pragma unroll
        for (int nf = 0; nf < 16; ++nf) {
            int jc = j0 + nf * 8 + colb;
            float2 b0 = *(const float2*)(bdr0 + jc);
            float2 b1 = *(const float2*)(bdr1 + jc);
            float s0 = (S[nf][0] + b0.x) * 0.125f;
            float s1 = (S[nf][1] + b0.y) * 0.125f;
            float s2 = (S[nf][2] + b1.x) * 0.125f;
            float s3 = (S[nf][3] + b1.y) * 0.125f;
            if (!nomask) {
                s0 = (jc     <= lim0) ? s0 : -1e30f;
                s1 = (jc + 1 <= lim0) ? s1 : -1e30f;
                s2 = (jc     <= lim1) ? s2 : -1e30f;
                s3 = (jc + 1 <= lim1) ? s3 : -1e30f;
            }
            S[nf][0] = s0; S[nf][1] = s1; S[nf][2] = s2; S[nf][3] = s3;
            mx0 = fmaxf(mx0, fmaxf(s0, s1));
            mx1 = fmaxf(mx1, fmaxf(s2, s3));
        }
        mx0 = fmaxf(mx0, __shfl_xor_sync(0xffffffffu, mx0, 1));
        mx0 = fmaxf(mx0, __shfl_xor_sync(0xffffffffu, mx0, 2));
        mx1 = fmaxf(mx1, __shfl_xor_sync(0xffffffffu, mx1, 1));
        mx1 = fmaxf(mx1, __shfl_xor_sync(0xffffffffu, mx1, 2));
        const float mnew0 = fmaxf(mold0, mx0);
        const float mnew1 = fmaxf(mold1, mx1);
        const float sc0 = __expf(mold0 - mnew0);
        const float sc1 = __expf(mold1 - mnew1);
        mold0 = mnew0; mold1 = mnew1;
        ssum0 *= sc0; ssum1 *= sc1;
#pragma unroll
        for (int nf = 0; nf < 8; ++nf) {
            pvacc[nf][0] *= sc0; pvacc[nf][1] *= sc0;
            pvacc[nf][2] *= sc1; pvacc[nf][3] *= sc1;
        }
#pragma unroll
        for (int nf = 0; nf < 16; ++nf) {
            S[nf][0] = __expf(S[nf][0] - mnew0);
            S[nf][1] = __expf(S[nf][1] - mnew0);
            S[nf][2] = __expf(S[nf][2] - mnew1);
            S[nf][3] = __expf(S[nf][3] - mnew1);
            ssum0 += S[nf][0] + S[nf][1];
            ssum1 += S[nf][2] + S[nf][3];
        }

        // ---- P @ V (x4.trans pair loads of V fragments) ----
#pragma unroll
        for (int kf = 0; kf < 8; ++kf) {
            uint32_t pah[4], pal[4];
            __nv_bfloat16 h0, l0, h1, l1;
            split1(S[2 * kf][0], h0, l0);     split1(S[2 * kf][1], h1, l1);
            pah[0] = pack2(h0, h1);           pal[0] = pack2(l0, l1);
            split1(S[2 * kf][2], h0, l0);     split1(S[2 * kf][3], h1, l1);
            pah[1] = pack2(h0, h1);           pal[1] = pack2(l0, l1);
            split1(S[2 * kf + 1][0], h0, l0); split1(S[2 * kf + 1][1], h1, l1);
            pah[2] = pack2(h0, h1);           pal[2] = pack2(l0, l1);
            split1(S[2 * kf + 1][2], h0, l0); split1(S[2 * kf + 1][3], h1, l1);
            pah[3] = pack2(h0, h1);           pal[3] = pack2(l0, l1);
#pragma unroll
            for (int nf2 = 0; nf2 < 4; ++nf2) {
                uint32_t baddr = vst + (kf * 16 + lane16) * SRS + (nf2 * 2 + bpair) * 16;
                uint32_t b4h[4], b4l[4];
                ldmx4t(b4h, baddr);
                ldmx4t(b4l, baddr + 18432u);
                mma16816(pvacc[2 * nf2],     pah, &b4h[0]);
                mma16816(pvacc[2 * nf2],     pah, &b4l[0]);
                mma16816(pvacc[2 * nf2],     pal, &b4h[0]);
                mma16816(pvacc[2 * nf2 + 1], pah, &b4h[2]);
                mma16816(pvacc[2 * nf2 + 1], pah, &b4l[2]);
                mma16816(pvacc[2 * nf2 + 1], pal, &b4h[2]);
            }
        }

        __syncthreads();
        if (c + 2 < nch) loadKV(c + 2);
        CP_COMMIT();
    }

    // ---- epilogue ----
    ssum0 += __shfl_xor_sync(0xffffffffu, ssum0, 1);
    ssum0 += __shfl_xor_sync(0xffffffffu, ssum0, 2);
    ssum1 += __shfl_xor_sync(0xffffffffu, ssum1, 1);
    ssum1 += __shfl_xor_sync(0xffffffffu, ssum1, 2);
    const float iv0 = 1.f / ssum0;
    const float iv1 = 1.f / ssum1;
    const size_t orow0 = (size_t)(b * QL + i0 + warp_m + r0) * DM + h * DH;
    const size_t orow1 = orow0 + (size_t)8 * DM;
#pragma unroll
    for (int nf = 0; nf < 8; ++nf) {
        int d = nf * 8 + colb;
        __nv_bfloat16 hh0, ll0, hh1, ll1;
        split1(pvacc[nf][0] * iv0, hh0, ll0);
        split1(pvacc[nf][1] * iv0, hh1, ll1);
        *(uint32_t*)(g_oh + orow0 + d) = pack2(hh0, hh1);
        *(uint32_t*)(g_ol + orow0 + d) = pack2(ll0, ll1);
        split1(pvacc[nf][2] * iv1, hh0, ll0);
        split1(pvacc[nf][3] * iv1, hh1, ll1);
        *(uint32_t*)(g_oh + orow1 + d) = pack2(hh0, hh1);
        *(uint32_t*)(g_ol + orow1 + d) = pack2(ll0, ll1);
    }
}

// =========================== launch =======================================
extern "C" void kernel_launch(void* const* d_in, const int* in_sizes, int n_in,
                              void* d_out, int out_size)
{
    const float* inputs = (const float*)d_in[0];
    const float* mem    = (const float*)d_in[1];
    const float* r      = (const float*)d_in[2];
    const float* W_qkv  = (const float*)d_in[3];
    const float* b_qkv  = (const float*)d_in[4];
    const float* W_r    = (const float*)d_in[5];
    const float* b_r    = (const float*)d_in[6];
    const float* W_o    = (const float*)d_in[7];
    const float* b_o    = (const float*)d_in[8];
    const float* u      = (const float*)d_in[9];
    const float* v      = (const float*)d_in[10];
    float* out = (float*)d_out;

    __nv_bfloat16 *pah, *pal, *prh, *prl, *poh, *pol;
    __nv_bfloat16 *pwqh, *pwql, *pwrh, *pwrl, *pwoh, *pwol;
    cudaGetSymbolAddress((void**)&pah,   g_ah);
    cudaGetSymbolAddress((void**)&pal,   g_al);
    cudaGetSymbolAddress((void**)&prh,   g_rh);
    cudaGetSymbolAddress((void**)&prl,   g_rl);
    cudaGetSymbolAddress((void**)&poh,   g_oh);
    cudaGetSymbolAddress((void**)&pol,   g_ol);
    cudaGetSymbolAddress((void**)&pwqh,  g_wqh);
    cudaGetSymbolAddress((void**)&pwql,  g_wql);
    cudaGetSymbolAddress((void**)&pwrh,  g_wrh);
    cudaGetSymbolAddress((void**)&pwrl,  g_wrl);
    cudaGetSymbolAddress((void**)&pwoh,  g_woh);
    cudaGetSymbolAddress((void**)&pwol,  g_wol);

    constexpr int SMEM_256 = 3 * (2 * 128 * 80 + 2 * 256 * 80);  // 184320
    constexpr int SMEM_128 = 3 * (2 * 128 * 80 + 2 * 128 * 80);  // 122880
    cudaFuncSetAttribute(gemm_bf3<1, 256>, cudaFuncAttributeMaxDynamicSharedMemorySize, SMEM_256);
    cudaFuncSetAttribute(gemm_bf3<2, 128>, cudaFuncAttributeMaxDynamicSharedMemorySize, SMEM_128);
    cudaFuncSetAttribute(gemm_bf3<0, 128>, cudaFuncAttributeMaxDynamicSharedMemorySize, SMEM_128);
    cudaFuncSetAttribute(bd_mma, cudaFuncAttributeMaxDynamicSharedMemorySize, SCORE_SMEM);
    cudaFuncSetAttribute(attn_flash, cudaFuncAttributeMaxDynamicSharedMemorySize, ATTN_SMEM);

    dim3 blk(256);

    // --- A-side / weight splits ---
    split_concat<<<4096, blk>>>(mem, inputs, pah, pal);
    split_plain<<<4096, blk>>>(r, prh, prl);
    split_transpose<<<dim3(3072 / 32, 1024 / 32), blk>>>(W_qkv, pwqh, pwql, 3072);
    split_transpose<<<dim3(1024 / 32, 1024 / 32), blk>>>(W_r,   pwrh, pwrl, 1024);
    split_transpose<<<dim3(1024 / 32, 1024 / 32), blk>>>(W_o,   pwoh, pwol, 1024);

    // 1) qkv projection (128x256 tile) with fused per-head operand epilogue
    gemm_bf3<1, 256><<<dim3(3072 / 256, 4096 / 128), blk, SMEM_256>>>(
        pah, pal, pwqh, pwql, b_qkv, nullptr, 3072, u, v);
    // 2) r projection with fused rr epilogue
    gemm_bf3<2, 128><<<dim3(1024 / 128, 4096 / 128), blk, SMEM_128>>>(
        prh, prl, pwrh, pwrl, b_r, nullptr, 1024, nullptr, nullptr);

    // 3) BD (pre-shifted) -> g_bd
    bd_mma<<<dim3(KL / 128, QL / 128, BQ * NH), blk, SCORE_SMEM>>>();

    // 4) fused AC + online softmax + P@V -> g_oh/g_ol
    attn_flash<<<dim3(QL / 128, BQ * NH), blk, ATTN_SMEM>>>();

    // 5) final projection -> d_out
    gemm_bf3<0, 128><<<dim3(1024 / 128, 2048 / 128), blk, SMEM_128>>>(
        poh, pol, pwoh, pwol, b_o, out, 1024, nullptr, nullptr);
}

// round 10
// speedup vs baseline: 1.0040x; 1.0040x over previous
#include <cuda_runtime.h>
#include <cuda_bf16.h>
#include <cstdint>
#include <cstddef>

#define BQ 2
#define QL 1024
#define ML 1024
#define KL 2048
#define DM 1024
#define NH 16
#define DH 64

// ---------------- scratch (device globals: allocation-free) ----------------
__device__ __nv_bfloat16 g_bd[(size_t)32 * 1024 * 2048];  // BD (pre-shifted, bf16)

__device__ __nv_bfloat16 g_ah[(size_t)4096 * 1024], g_al[(size_t)4096 * 1024];
__device__ __nv_bfloat16 g_rh[(size_t)4096 * 1024], g_rl[(size_t)4096 * 1024];
__device__ __nv_bfloat16 g_oh[(size_t)2048 * 1024], g_ol[(size_t)2048 * 1024];
__device__ __nv_bfloat16 g_wqh[(size_t)3072 * 1024], g_wql[(size_t)3072 * 1024];
__device__ __nv_bfloat16 g_wrh[(size_t)1024 * 1024], g_wrl[(size_t)1024 * 1024];
__device__ __nv_bfloat16 g_woh[(size_t)1024 * 1024], g_wol[(size_t)1024 * 1024];

__device__ __nv_bfloat16 g_quh[(size_t)32 * 1024 * 64], g_qul[(size_t)32 * 1024 * 64];
__device__ __nv_bfloat16 g_qvh[(size_t)32 * 1024 * 64], g_qvl[(size_t)32 * 1024 * 64];
__device__ __nv_bfloat16 g_khh[(size_t)32 * 2048 * 64], g_khl[(size_t)32 * 2048 * 64];
__device__ __nv_bfloat16 g_rrh[(size_t)32 * 2048 * 64], g_rrl[(size_t)32 * 2048 * 64];
__device__ __nv_bfloat16 g_vjh[(size_t)32 * 2048 * 64], g_vjl[(size_t)32 * 2048 * 64];

// ======================= helpers ===========================================
__device__ __forceinline__ uint32_t smem_u32(const void* p) {
    uint32_t a;
    asm("{ .reg .u64 t; cvta.to.shared.u64 t, %1; cvt.u32.u64 %0, t; }"
        : "=r"(a) : "l"(p));
    return a;
}
__device__ __forceinline__ void split1(float x, __nv_bfloat16& h, __nv_bfloat16& l) {
    h = __float2bfloat16_rn(x);
    l = __float2bfloat16_rn(x - __bfloat162float(h));
}
__device__ __forceinline__ uint32_t pack2(__nv_bfloat16 a, __nv_bfloat16 b) {
    __nv_bfloat162 v = make_bfloat162(a, b);
    return *(uint32_t*)&v;
}
__device__ __forceinline__ void ldmx4(uint32_t a[4], uint32_t addr) {
    asm volatile("ldmatrix.sync.aligned.m8n8.x4.shared.b16 {%0,%1,%2,%3}, [%4];"
        : "=r"(a[0]), "=r"(a[1]), "=r"(a[2]), "=r"(a[3]) : "r"(addr));
}
__device__ __forceinline__ void ldmx2(uint32_t a[2], uint32_t addr) {
    asm volatile("ldmatrix.sync.aligned.m8n8.x2.shared.b16 {%0,%1}, [%2];"
        : "=r"(a[0]), "=r"(a[1]) : "r"(addr));
}
__device__ __forceinline__ void ldmx2t(uint32_t a[2], uint32_t addr) {
    asm volatile("ldmatrix.sync.aligned.m8n8.x2.trans.shared.b16 {%0,%1}, [%2];"
        : "=r"(a[0]), "=r"(a[1]) : "r"(addr));
}
__device__ __forceinline__ void mma16816(float c[4], const uint32_t a[4], const uint32_t b[2]) {
    asm volatile("mma.sync.aligned.m16n8k16.row.col.f32.bf16.bf16.f32 "
        "{%0,%1,%2,%3}, {%4,%5,%6,%7}, {%8,%9}, {%0,%1,%2,%3};"
        : "+f"(c[0]), "+f"(c[1]), "+f"(c[2]), "+f"(c[3])
        : "r"(a[0]), "r"(a[1]), "r"(a[2]), "r"(a[3]), "r"(b[0]), "r"(b[1]));
}
#define CP16(dst, src) \
    asm volatile("cp.async.cg.shared.global [%0], [%1], 16;" :: "r"(dst), "l"(src) : "memory")
#define CP_COMMIT() asm volatile("cp.async.commit_group;" ::: "memory")
#define CP_WAIT(n)  asm volatile("cp.async.wait_group %0;" :: "n"(n) : "memory")

// ===================== prep: split kernels ==================================
__global__ __launch_bounds__(256)
void split_concat(const float* __restrict__ mem, const float* __restrict__ inp,
                  __nv_bfloat16* __restrict__ hi, __nv_bfloat16* __restrict__ lo)
{
    size_t idx = ((size_t)blockIdx.x * 256 + threadIdx.x) * 4;
    size_t row = idx >> 10;
    int col = (int)(idx & 1023);
    int b = (int)(row >> 11);
    int k = (int)(row & 2047);
    const float* src = (k < ML) ? mem + ((size_t)(b * ML + k) << 10)
                                : inp + ((size_t)(b * QL + (k - ML)) << 10);
    float4 v = *(const float4*)(src + col);
    __nv_bfloat16 h0, h1, h2, h3, l0, l1, l2, l3;
    split1(v.x, h0, l0); split1(v.y, h1, l1);
    split1(v.z, h2, l2); split1(v.w, h3, l3);
    __nv_bfloat162* H = (__nv_bfloat162*)(hi + idx);
    __nv_bfloat162* L = (__nv_bfloat162*)(lo + idx);
    H[0] = make_bfloat162(h0, h1); H[1] = make_bfloat162(h2, h3);
    L[0] = make_bfloat162(l0, l1); L[1] = make_bfloat162(l2, l3);
}

__global__ __launch_bounds__(256)
void split_plain(const float* __restrict__ src,
                 __nv_bfloat16* __restrict__ hi, __nv_bfloat16* __restrict__ lo)
{
    size_t idx = ((size_t)blockIdx.x * 256 + threadIdx.x) * 4;
    float4 v = *(const float4*)(src + idx);
    __nv_bfloat16 h0, h1, h2, h3, l0, l1, l2, l3;
    split1(v.x, h0, l0); split1(v.y, h1, l1);
    split1(v.z, h2, l2); split1(v.w, h3, l3);
    __nv_bfloat162* H = (__nv_bfloat162*)(hi + idx);
    __nv_bfloat162* L = (__nv_bfloat162*)(lo + idx);
    H[0] = make_bfloat162(h0, h1); H[1] = make_bfloat162(h2, h3);
    L[0] = make_bfloat162(l0, l1); L[1] = make_bfloat162(l2, l3);
}

__global__ __launch_bounds__(256)
void split_transpose(const float* __restrict__ in,
                     __nv_bfloat16* __restrict__ hi, __nv_bfloat16* __restrict__ lo, int N)
{
    __shared__ float s[32][33];
    const int nx = blockIdx.x * 32;
    const int ky = blockIdx.y * 32;
    const int tx = threadIdx.x & 31;
    const int ty = threadIdx.x >> 5;
#pragma unroll
    for (int r = 0; r < 32; r += 8)
        s[ty + r][tx] = in[(size_t)(ky + ty + r) * N + nx + tx];
    __syncthreads();
#pragma unroll
    for (int r = 0; r < 32; r += 8) {
        float x = s[tx][ty + r];
        __nv_bfloat16 h, l;
        split1(x, h, l);
        size_t o = (size_t)(nx + ty + r) * DM + ky + tx;
        hi[o] = h;
        lo[o] = l;
    }
}

// ============== dense GEMM: mma.sync bf16 3-term split ======================
// MODE 0: fp32 C out.  MODE 1: qkv epilogue -> per-head operands.  MODE 2: rr.
#define RS 80
#define ARRB (128 * RS)
#define STGB (4 * ARRB)
#define NSTG 4
#define GEMM_SMEM (NSTG * STGB)

template<int MODE>
__device__ __forceinline__ void store_opnd(int m, int n, float x0, float x1,
                                           const float* __restrict__ u,
                                           const float* __restrict__ v)
{
    int b = m >> 11, tok = m & 2047;
    __nv_bfloat16 h0, l0, h1, l1;
    if (MODE == 2) {
        int h = n >> 6, d = n & 63;
        size_t o = ((size_t)(b * NH + h) * KL + tok) * DH + d;
        split1(x0, h0, l0); split1(x1, h1, l1);
        *(uint32_t*)(g_rrh + o) = pack2(h0, h1);
        *(uint32_t*)(g_rrl + o) = pack2(l0, l1);
    } else if (n < 1024) {
        int h = n >> 6, d = n & 63, i = tok - ML;
        size_t o = ((size_t)(b * NH + h) * QL + i) * DH + d;
        split1(x0 + u[n], h0, l0); split1(x1 + u[n + 1], h1, l1);
        *(uint32_t*)(g_quh + o) = pack2(h0, h1);
        *(uint32_t*)(g_qul + o) = pack2(l0, l1);
        split1(x0 + v[n], h0, l0); split1(x1 + v[n + 1], h1, l1);
        *(uint32_t*)(g_qvh + o) = pack2(h0, h1);
        *(uint32_t*)(g_qvl + o) = pack2(l0, l1);
    } else if (n < 2048) {
        int h = (n - 1024) >> 6, d = n & 63;
        size_t o = ((size_t)(b * NH + h) * KL + tok) * DH + d;
        split1(x0, h0, l0); split1(x1, h1, l1);
        *(uint32_t*)(g_vjh + o) = pack2(h0, h1);
        *(uint32_t*)(g_vjl + o) = pack2(l0, l1);
    } else {
        int h = (n - 2048) >> 6, d = n & 63;
        size_t o = ((size_t)(b * NH + h) * KL + tok) * DH + d;
        split1(x0, h0, l0); split1(x1, h1, l1);
        *(uint32_t*)(g_khh + o) = pack2(h0, h1);
        *(uint32_t*)(g_khl + o) = pack2(l0, l1);
    }
}

template<int MODE>
__global__ __launch_bounds__(256, 1)
void gemm_bf3(const __nv_bfloat16* __restrict__ Ah, const __nv_bfloat16* __restrict__ Al,
              const __nv_bfloat16* __restrict__ Bh, const __nv_bfloat16* __restrict__ Bl,
              const float* __restrict__ bias, float* __restrict__ C, int N,
              const float* __restrict__ u, const float* __restrict__ v)
{
    extern __shared__ char sm[];
    const uint32_t sb = smem_u32(sm);
    const int t = threadIdx.x;
    const int lane = t & 31;
    const int wid = t >> 5;
    const int m0 = blockIdx.y * 128;
    const int n0 = blockIdx.x * 128;
    if (MODE == 1 && n0 < 1024 && ((m0 & 2047) + 128) <= ML) return;

    const int warp_m = (wid & 1) * 64;
    const int warp_n = (wid >> 1) * 32;

    const __nv_bfloat16* srcs[4] = {
        Ah + (size_t)m0 * DM, Al + (size_t)m0 * DM,
        Bh + (size_t)n0 * DM, Bl + (size_t)n0 * DM
    };

    auto issue_stage = [&](int c) {
        uint32_t dst0 = sb + (uint32_t)(c & 3) * STGB;
#pragma unroll
        for (int arr = 0; arr < 4; ++arr) {
#pragma unroll
            for (int rep = 0; rep < 2; ++rep) {
                int ci = t + rep * 256;
                int row = ci >> 2;
                int kc = ci & 3;
                uint32_t dst = dst0 + arr * ARRB + row * RS + kc * 16;
                const __nv_bfloat16* src = srcs[arr] + (size_t)row * DM + c * 32 + kc * 8;
                CP16(dst, src);
            }
        }
    };

    float acc[4][4][4];
#pragma unroll
    for (int im = 0; im < 4; ++im)
#pragma unroll
        for (int jn = 0; jn < 4; ++jn)
#pragma unroll
            for (int q = 0; q < 4; ++q) acc[im][jn][q] = 0.f;

#pragma unroll
    for (int s = 0; s < NSTG - 1; ++s) { issue_stage(s); CP_COMMIT(); }

    const int NCH = DM / 32;
    for (int c = 0; c < NCH; ++c) {
        CP_WAIT(2);
        __syncthreads();
        if (c + 3 < NCH) issue_stage(c + 3);
        CP_COMMIT();

        const uint32_t st = sb + (uint32_t)(c & 3) * STGB;
        const int mrow = lane & 15;
        const int khalf = lane >> 4;
        const int nrow = lane & 7;
        const int khalfb = (lane >> 3) & 1;
#pragma unroll
        for (int kk = 0; kk < 32; kk += 16) {
            uint32_t ah[4][4], al[4][4], bh[4][2], bl[4][2];
#pragma unroll
            for (int im = 0; im < 4; ++im) {
                uint32_t aaddr = st + (warp_m + im * 16 + mrow) * RS + (kk + khalf * 8) * 2;
                ldmx4(ah[im], aaddr);
                ldmx4(al[im], aaddr + ARRB);
            }
#pragma unroll
            for (int jn = 0; jn < 4; ++jn) {
                uint32_t baddr = st + 2 * ARRB + (warp_n + jn * 8 + nrow) * RS + (kk + khalfb * 8) * 2;
                ldmx2(bh[jn], baddr);
                ldmx2(bl[jn], baddr + ARRB);
            }
#pragma unroll
            for (int im = 0; im < 4; ++im)
#pragma unroll
                for (int jn = 0; jn < 4; ++jn) {
                    mma16816(acc[im][jn], ah[im], bh[jn]);
                    mma16816(acc[im][jn], ah[im], bl[jn]);
                    mma16816(acc[im][jn], al[im], bh[jn]);
                }
        }
    }

    if (MODE == 0) {
#pragma unroll
        for (int im = 0; im < 4; ++im) {
            int m = m0 + warp_m + im * 16 + (lane >> 2);
#pragma unroll
            for (int jn = 0; jn < 4; ++jn) {
                int n = n0 + warp_n + jn * 8 + (lane & 3) * 2;
                float b0 = bias[n], b1 = bias[n + 1];
                float2 v0, v1;
                v0.x = acc[im][jn][0] + b0; v0.y = acc[im][jn][1] + b1;
                v1.x = acc[im][jn][2] + b0; v1.y = acc[im][jn][3] + b1;
                *(float2*)(C + (size_t)m * N + n) = v0;
                *(float2*)(C + (size_t)(m + 8) * N + n) = v1;
            }
        }
    } else {
#pragma unroll
        for (int im = 0; im < 4; ++im) {
            int m = m0 + warp_m + im * 16 + (lane >> 2);
#pragma unroll
            for (int jn = 0; jn < 4; ++jn) {
                int n = n0 + warp_n + jn * 8 + (lane & 3) * 2;
                float b0 = bias[n], b1 = bias[n + 1];
                store_opnd<MODE>(m, n, acc[im][jn][0] + b0, acc[im][jn][1] + b1, u, v);
                store_opnd<MODE>(m + 8, n, acc[im][jn][2] + b0, acc[im][jn][3] + b1, u, v);
            }
        }
    }
}

// ============== BD score GEMM (mma, K=64, pre-shifted bf16 scatter) =========
#define SRS 144
#define SARRB (128 * SRS)
#define SCORE_SMEM (4 * SARRB)

__global__ __launch_bounds__(256, 1)
void bd_mma()
{
    const int bh = blockIdx.z;
    const int i0 = blockIdx.y * 128;
    const int p0 = blockIdx.x * 128;
    if (i0 + p0 + 254 < QL - 1) return;

    extern __shared__ char sm[];
    const uint32_t sb = smem_u32(sm);
    const int t = threadIdx.x;
    const int lane = t & 31;
    const int wid = t >> 5;
    const int warp_m = (wid & 1) * 64;
    const int warp_n = (wid >> 1) * 32;

    const __nv_bfloat16* srcs[4] = {
        g_qvh + ((size_t)bh * QL + i0) * DH,
        g_qvl + ((size_t)bh * QL + i0) * DH,
        g_rrh + ((size_t)bh * KL + p0) * DH,
        g_rrl + ((size_t)bh * KL + p0) * DH
    };
#pragma unroll
    for (int arr = 0; arr < 4; ++arr) {
#pragma unroll
        for (int rep = 0; rep < 4; ++rep) {
            int ci = t + rep * 256;
            int row = ci >> 3;
            int kc = ci & 7;
            uint32_t dst = sb + arr * SARRB + row * SRS + kc * 16;
            CP16(dst, srcs[arr] + (size_t)row * DH + kc * 8);
        }
    }
    CP_COMMIT();
    CP_WAIT(0);
    __syncthreads();

    float acc[4][4][4];
#pragma unroll
    for (int im = 0; im < 4; ++im)
#pragma unroll
        for (int jn = 0; jn < 4; ++jn)
#pragma unroll
            for (int q = 0; q < 4; ++q) acc[im][jn][q] = 0.f;

    const int mrow = lane & 15;
    const int khalf = lane >> 4;
    const int nrow = lane & 7;
    const int khalfb = (lane >> 3) & 1;
#pragma unroll
    for (int kk = 0; kk < 64; kk += 16) {
        uint32_t ah[4][4], al[4][4], bh[4][2], bl[4][2];
#pragma unroll
        for (int im = 0; im < 4; ++im) {
            uint32_t aaddr = sb + (warp_m + im * 16 + mrow) * SRS + (kk + khalf * 8) * 2;
            ldmx4(ah[im], aaddr);
            ldmx4(al[im], aaddr + SARRB);
        }
#pragma unroll
        for (int jn = 0; jn < 4; ++jn) {
            uint32_t baddr = sb + 2 * SARRB + (warp_n + jn * 8 + nrow) * SRS + (kk + khalfb * 8) * 2;
            ldmx2(bh[jn], baddr);
            ldmx2(bl[jn], baddr + SARRB);
        }
#pragma unroll
        for (int im = 0; im < 4; ++im)
#pragma unroll
            for (int jn = 0; jn < 4; ++jn) {
                mma16816(acc[im][jn], ah[im], bh[jn]);
                mma16816(acc[im][jn], ah[im], bl[jn]);
                mma16816(acc[im][jn], al[im], bh[jn]);
            }
    }

#pragma unroll
    for (int im = 0; im < 4; ++im) {
        int m = i0 + warp_m + im * 16 + (lane >> 2);
        __nv_bfloat16* r0 = g_bd + ((size_t)bh * QL + m) * KL;
        __nv_bfloat16* r1 = g_bd + ((size_t)bh * QL + m + 8) * KL;
        int sh0 = m - (QL - 1);
        int sh1 = m + 8 - (QL - 1);
#pragma unroll
        for (int jn = 0; jn < 4; ++jn) {
            int p = p0 + warp_n + jn * 8 + (lane & 3) * 2;
            int j0a = p + sh0;
            int j1a = p + sh1;
            if (j0a >= 0)     r0[j0a]     = __float2bfloat16_rn(acc[im][jn][0]);
            if (j0a + 1 >= 0) r0[j0a + 1] = __float2bfloat16_rn(acc[im][jn][1]);
            if (j1a >= 0)     r1[j1a]     = __float2bfloat16_rn(acc[im][jn][2]);
            if (j1a + 1 >= 0) r1[j1a + 1] = __float2bfloat16_rn(acc[im][jn][3]);
        }
    }
}

// ========== warp-autonomous flash attention: AC in-register + PV ===========
#define FCH 128
#define AQ_OFF 0u
#define AK_OFF 36864u
#define AV_OFF 110592u
#define ABUF 36864u
#define ATTN_SMEM 184320

__global__ __launch_bounds__(256, 1)
void attn_flash()
{
    extern __shared__ char sm[];
    const uint32_t sb = smem_u32(sm);
    const int bh = blockIdx.y;
    const int b = bh >> 4, h = bh & 15;
    const int i0 = (gridDim.x - 1 - blockIdx.x) * 128;
    const int t = threadIdx.x, lane = t & 31, wid = t >> 5;
    const int warp_m = wid * 16;

    const __nv_bfloat16* Kh  = g_khh + (size_t)bh * KL * DH;
    const __nv_bfloat16* Klo = g_khl + (size_t)bh * KL * DH;
    const __nv_bfloat16* Vjh = g_vjh + (size_t)bh * KL * DH;
    const __nv_bfloat16* Vjl = g_vjl + (size_t)bh * KL * DH;

    {
        const __nv_bfloat16* Qh = g_quh + ((size_t)bh * QL + i0) * DH;
        const __nv_bfloat16* Ql = g_qul + ((size_t)bh * QL + i0) * DH;
#pragma unroll
        for (int rep = 0; rep < 4; ++rep) {
            int ci = t + rep * 256;
            int row = ci >> 3, kc = ci & 7;
            uint32_t dst = sb + AQ_OFF + row * SRS + kc * 16;
            CP16(dst, Qh + (size_t)row * DH + kc * 8);
            CP16(dst + 18432u, Ql + (size_t)row * DH + kc * 8);
        }
    }
    CP_COMMIT();

    auto loadKV = [&](int c) {
        uint32_t kd = sb + AK_OFF + (uint32_t)(c & 1) * ABUF;
        uint32_t vd = sb + AV_OFF + (uint32_t)(c & 1) * ABUF;
#pragma unroll
        for (int rep = 0; rep < 4; ++rep) {
            int ci = t + rep * 256;
            int row = ci >> 3, kc = ci & 7;
            uint32_t o = row * SRS + kc * 16;
            CP16(kd + o, Kh + (size_t)(c * FCH + row) * DH + kc * 8);
            CP16(kd + o + 18432u, Klo + (size_t)(c * FCH + row) * DH + kc * 8);
            CP16(vd + o, Vjh + (size_t)(c * FCH + row) * DH + kc * 8);
            CP16(vd + o + 18432u, Vjl + (size_t)(c * FCH + row) * DH + kc * 8);
        }
    };

    const int nch = (ML + i0 + 128) / FCH;
    loadKV(0); CP_COMMIT();
    loadKV(1); CP_COMMIT();

    const int mrow = lane & 15, khalf = lane >> 4;
    const int nrow = lane & 7, khalfb = (lane >> 3) & 1;
    const int lane16 = lane & 15;
    uint32_t aqh[4][4], aql[4][4];
    CP_WAIT(2);
    __syncthreads();
#pragma unroll
    for (int kf = 0; kf < 4; ++kf) {
        uint32_t aaddr = sb + AQ_OFF + (warp_m + mrow) * SRS + (kf * 16 + khalf * 8) * 2;
        ldmx4(aqh[kf], aaddr);
        ldmx4(aql[kf], aaddr + 18432u);
    }

    const int r0 = lane >> 2;
    const int colb = (lane & 3) * 2;
    const __nv_bfloat16* bdr0 = g_bd + ((size_t)bh * QL + i0 + warp_m + r0) * KL;
    const __nv_bfloat16* bdr1 = bdr0 + (size_t)8 * KL;
    const int lim0 = ML + i0 + warp_m + r0;
    const int lim1 = lim0 + 8;

    float pvacc[8][4];
#pragma unroll
    for (int nf = 0; nf < 8; ++nf)
#pragma unroll
        for (int q = 0; q < 4; ++q) pvacc[nf][q] = 0.f;
    float ssum0 = 0.f, ssum1 = 0.f;
    float mold0 = -1e30f, mold1 = -1e30f;

    for (int c = 0; c < nch; ++c) {
        CP_WAIT(1);
        __syncthreads();
        const uint32_t kst = sb + AK_OFF + (uint32_t)(c & 1) * ABUF;
        const uint32_t vst = sb + AV_OFF + (uint32_t)(c & 1) * ABUF;
        const int j0 = c * FCH;

        // ---- S = (q+u) . K^T ----
        float S[16][4];
#pragma unroll
        for (int nf = 0; nf < 16; ++nf) {
            S[nf][0] = S[nf][1] = S[nf][2] = S[nf][3] = 0.f;
#pragma unroll
            for (int kf = 0; kf < 4; ++kf) {
                uint32_t bhh[2], bll[2];
                uint32_t baddr = kst + (nf * 8 + nrow) * SRS + (kf * 16 + khalfb * 8) * 2;
                ldmx2(bhh, baddr);
                ldmx2(bll, baddr + 18432u);
                mma16816(S[nf], aqh[kf], bhh);
                mma16816(S[nf], aqh[kf], bll);
                mma16816(S[nf], aql[kf], bhh);
            }
        }

        // ---- + BD (bf16x2 aligned reads), scale, mask, row max ----
        const bool nomask = (j0 + 127) <= lim0;
        float mx0 = -1e30f, mx1 = -1e30f;
#pragma unroll
        for (int nf = 0; nf < 16; ++nf) {
            int jc = j0 + nf * 8 + colb;
            float2 b0 = __bfloat1622float2(*(const __nv_bfloat162*)(bdr0 + jc));
            float2 b1 = __bfloat1622float2(*(const __nv_bfloat162*)(bdr1 + jc));
            float s0 = (S[nf][0] + b0.x) * 0.125f;
            float s1 = (S[nf][1] + b0.y) * 0.125f;
            float s2 = (S[nf][2] + b1.x) * 0.125f;
            float s3 = (S[nf][3] + b1.y) * 0.125f;
            if (!nomask) {
                s0 = (jc     <= lim0) ? s0 : -1e30f;
                s1 = (jc + 1 <= lim0) ? s1 : -1e30f;
                s2 = (jc     <= lim1) ? s2 : -1e30f;
                s3 = (jc + 1 <= lim1) ? s3 : -1e30f;
            }
            S[nf][0] = s0; S[nf][1] = s1; S[nf][2] = s2; S[nf][3] = s3;
            mx0 = fmaxf(mx0, fmaxf(s0, s1));
            mx1 = fmaxf(mx1, fmaxf(s2, s3));
        }
        mx0 = fmaxf(mx0, __shfl_xor_sync(0xffffffffu, mx0, 1));
        mx0 = fmaxf(mx0, __shfl_xor_sync(0xffffffffu, mx0, 2));
        mx1 = fmaxf(mx1, __shfl_xor_sync(0xffffffffu, mx1, 1));
        mx1 = fmaxf(mx1, __shfl_xor_sync(0xffffffffu, mx1, 2));
        const float mnew0 = fmaxf(mold0, mx0);
        const float mnew1 = fmaxf(mold1, mx1);
        const float sc0 = __expf(mold0 - mnew0);
        const float sc1 = __expf(mold1 - mnew1);
        mold0 = mnew0; mold1 = mnew1;
        ssum0 *= sc0; ssum1 *= sc1;
#pragma unroll
        for (int nf = 0; nf < 8; ++nf) {
            pvacc[nf][0] *= sc0; pvacc[nf][1] *= sc0;
            pvacc[nf][2] *= sc1; pvacc[nf][3] *= sc1;
        }
#pragma unroll
        for (int nf = 0; nf < 16; ++nf) {
            S[nf][0] = __expf(S[nf][0] - mnew0);
            S[nf][1] = __expf(S[nf][1] - mnew0);
            S[nf][2] = __expf(S[nf][2] - mnew1);
            S[nf][3] = __expf(S[nf][3] - mnew1);
            ssum0 += S[nf][0] + S[nf][1];
            ssum1 += S[nf][2] + S[nf][3];
        }

        // ---- P (bf16 hi/lo from fragments) @ V (ldmatrix.trans of [j][d]) ----
#pragma unroll
        for (int kf = 0; kf < 8; ++kf) {
            uint32_t pah[4], pal[4];
            __nv_bfloat16 h0, l0, h1, l1;
            split1(S[2 * kf][0], h0, l0);     split1(S[2 * kf][1], h1, l1);
            pah[0] = pack2(h0, h1);           pal[0] = pack2(l0, l1);
            split1(S[2 * kf][2], h0, l0);     split1(S[2 * kf][3], h1, l1);
            pah[1] = pack2(h0, h1);           pal[1] = pack2(l0, l1);
            split1(S[2 * kf + 1][0], h0, l0); split1(S[2 * kf + 1][1], h1, l1);
            pah[2] = pack2(h0, h1);           pal[2] = pack2(l0, l1);
            split1(S[2 * kf + 1][2], h0, l0); split1(S[2 * kf + 1][3], h1, l1);
            pah[3] = pack2(h0, h1);           pal[3] = pack2(l0, l1);
#pragma unroll
            for (int nf = 0; nf < 8; ++nf) {
                uint32_t bhh[2], bll[2];
                uint32_t baddr = vst + (kf * 16 + lane16) * SRS + nf * 16;
                ldmx2t(bhh, baddr);
                ldmx2t(bll, baddr + 18432u);
                mma16816(pvacc[nf], pah, bhh);
                mma16816(pvacc[nf], pah, bll);
                mma16816(pvacc[nf], pal, bhh);
            }
        }

        __syncthreads();
        if (c + 2 < nch) loadKV(c + 2);
        CP_COMMIT();
    }

    // ---- epilogue: normalize, split to bf16 hi/lo, store to g_oh/g_ol ----
    ssum0 += __shfl_xor_sync(0xffffffffu, ssum0, 1);
    ssum0 += __shfl_xor_sync(0xffffffffu, ssum0, 2);
    ssum1 += __shfl_xor_sync(0xffffffffu, ssum1, 1);
    ssum1 += __shfl_xor_sync(0xffffffffu, ssum1, 2);
    const float iv0 = 1.f / ssum0;
    const float iv1 = 1.f / ssum1;
    const size_t orow0 = (size_t)(b * QL + i0 + warp_m + r0) * DM + h * DH;
    const size_t orow1 = orow0 + (size_t)8 * DM;
#pragma unroll
    for (int nf = 0; nf < 8; ++nf) {
        int d = nf * 8 + colb;
        __nv_bfloat16 hh0, ll0, hh1, ll1;
        split1(pvacc[nf][0] * iv0, hh0, ll0);
        split1(pvacc[nf][1] * iv0, hh1, ll1);
        *(uint32_t*)(g_oh + orow0 + d) = pack2(hh0, hh1);
        *(uint32_t*)(g_ol + orow0 + d) = pack2(ll0, ll1);
        split1(pvacc[nf][2] * iv1, hh0, ll0);
        split1(pvacc[nf][3] * iv1, hh1, ll1);
        *(uint32_t*)(g_oh + orow1 + d) = pack2(hh0, hh1);
        *(uint32_t*)(g_ol + orow1 + d) = pack2(ll0, ll1);
    }
}

// =========================== launch =======================================
extern "C" void kernel_launch(void* const* d_in, const int* in_sizes, int n_in,
                              void* d_out, int out_size)
{
    const float* inputs = (const float*)d_in[0];
    const float* mem    = (const float*)d_in[1];
    const float* r      = (const float*)d_in[2];
    const float* W_qkv  = (const float*)d_in[3];
    const float* b_qkv  = (const float*)d_in[4];
    const float* W_r    = (const float*)d_in[5];
    const float* b_r    = (const float*)d_in[6];
    const float* W_o    = (const float*)d_in[7];
    const float* b_o    = (const float*)d_in[8];
    const float* u      = (const float*)d_in[9];
    const float* v      = (const float*)d_in[10];
    float* out = (float*)d_out;

    __nv_bfloat16 *pah, *pal, *prh, *prl, *poh, *pol;
    __nv_bfloat16 *pwqh, *pwql, *pwrh, *pwrl, *pwoh, *pwol;
    cudaGetSymbolAddress((void**)&pah,   g_ah);
    cudaGetSymbolAddress((void**)&pal,   g_al);
    cudaGetSymbolAddress((void**)&prh,   g_rh);
    cudaGetSymbolAddress((void**)&prl,   g_rl);
    cudaGetSymbolAddress((void**)&poh,   g_oh);
    cudaGetSymbolAddress((void**)&pol,   g_ol);
    cudaGetSymbolAddress((void**)&pwqh,  g_wqh);
    cudaGetSymbolAddress((void**)&pwql,  g_wql);
    cudaGetSymbolAddress((void**)&pwrh,  g_wrh);
    cudaGetSymbolAddress((void**)&pwrl,  g_wrl);
    cudaGetSymbolAddress((void**)&pwoh,  g_woh);
    cudaGetSymbolAddress((void**)&pwol,  g_wol);

    cudaFuncSetAttribute(gemm_bf3<0>, cudaFuncAttributeMaxDynamicSharedMemorySize, GEMM_SMEM);
    cudaFuncSetAttribute(gemm_bf3<1>, cudaFuncAttributeMaxDynamicSharedMemorySize, GEMM_SMEM);
    cudaFuncSetAttribute(gemm_bf3<2>, cudaFuncAttributeMaxDynamicSharedMemorySize, GEMM_SMEM);
    cudaFuncSetAttribute(bd_mma, cudaFuncAttributeMaxDynamicSharedMemorySize, SCORE_SMEM);
    cudaFuncSetAttribute(attn_flash, cudaFuncAttributeMaxDynamicSharedMemorySize, ATTN_SMEM);

    dim3 blk(256);

    // --- A-side / weight splits ---
    split_concat<<<4096, blk>>>(mem, inputs, pah, pal);
    split_plain<<<4096, blk>>>(r, prh, prl);
    split_transpose<<<dim3(3072 / 32, 1024 / 32), blk>>>(W_qkv, pwqh, pwql, 3072);
    split_transpose<<<dim3(1024 / 32, 1024 / 32), blk>>>(W_r,   pwrh, pwrl, 1024);
    split_transpose<<<dim3(1024 / 32, 1024 / 32), blk>>>(W_o,   pwoh, pwol, 1024);

    // 1) qkv projection with fused per-head operand epilogue
    gemm_bf3<1><<<dim3(3072 / 128, 4096 / 128), blk, GEMM_SMEM>>>(
        pah, pal, pwqh, pwql, b_qkv, nullptr, 3072, u, v);
    // 2) r projection with fused rr epilogue
    gemm_bf3<2><<<dim3(1024 / 128, 4096 / 128), blk, GEMM_SMEM>>>(
        prh, prl, pwrh, pwrl, b_r, nullptr, 1024, nullptr, nullptr);

    // 3) BD (pre-shifted, bf16) -> g_bd
    bd_mma<<<dim3(KL / 128, QL / 128, BQ * NH), blk, SCORE_SMEM>>>();

    // 4) fused AC + online softmax + P@V -> g_oh/g_ol
    attn_flash<<<dim3(QL / 128, BQ * NH), blk, ATTN_SMEM>>>();

    // 5) final projection -> d_out
    gemm_bf3<0><<<dim3(1024 / 128, 2048 / 128), blk, GEMM_SMEM>>>(
        poh, pol, pwoh, pwol, b_o, out, 1024, nullptr, nullptr);
}

// round 11
// speedup vs baseline: 1.0491x; 1.0450x over previous
#include <cuda_runtime.h>
#include <cuda_bf16.h>
#include <cstdint>
#include <cstddef>

#define BQ 2
#define QL 1024
#define ML 1024
#define KL 2048
#define DM 1024
#define NH 16
#define DH 64

// ---------------- scratch (device globals: allocation-free) ----------------
__device__ float g_bd[(size_t)32 * 1024 * 2048];    // BD (pre-shifted) [B*H, Q, K]

__device__ __nv_bfloat16 g_ah[(size_t)4096 * 1024], g_al[(size_t)4096 * 1024];
__device__ __nv_bfloat16 g_rh[(size_t)4096 * 1024], g_rl[(size_t)4096 * 1024];
__device__ __nv_bfloat16 g_oh[(size_t)2048 * 1024], g_ol[(size_t)2048 * 1024];
__device__ __nv_bfloat16 g_wqh[(size_t)3072 * 1024], g_wql[(size_t)3072 * 1024];
__device__ __nv_bfloat16 g_wrh[(size_t)1024 * 1024], g_wrl[(size_t)1024 * 1024];
__device__ __nv_bfloat16 g_woh[(size_t)1024 * 1024], g_wol[(size_t)1024 * 1024];

__device__ __nv_bfloat16 g_quh[(size_t)32 * 1024 * 64], g_qul[(size_t)32 * 1024 * 64];
__device__ __nv_bfloat16 g_qvh[(size_t)32 * 1024 * 64], g_qvl[(size_t)32 * 1024 * 64];
__device__ __nv_bfloat16 g_khh[(size_t)32 * 2048 * 64], g_khl[(size_t)32 * 2048 * 64];
__device__ __nv_bfloat16 g_rrh[(size_t)32 * 2048 * 64], g_rrl[(size_t)32 * 2048 * 64];
__device__ __nv_bfloat16 g_vjh[(size_t)32 * 2048 * 64], g_vjl[(size_t)32 * 2048 * 64];

// ======================= helpers ===========================================
__device__ __forceinline__ uint32_t smem_u32(const void* p) {
    uint32_t a;
    asm("{ .reg .u64 t; cvta.to.shared.u64 t, %1; cvt.u32.u64 %0, t; }"
        : "=r"(a) : "l"(p));
    return a;
}
__device__ __forceinline__ void split1(float x, __nv_bfloat16& h, __nv_bfloat16& l) {
    h = __float2bfloat16_rn(x);
    l = __float2bfloat16_rn(x - __bfloat162float(h));
}
__device__ __forceinline__ uint32_t pack2(__nv_bfloat16 a, __nv_bfloat16 b) {
    __nv_bfloat162 v = make_bfloat162(a, b);
    return *(uint32_t*)&v;
}
__device__ __forceinline__ void ldmx4(uint32_t a[4], uint32_t addr) {
    asm volatile("ldmatrix.sync.aligned.m8n8.x4.shared.b16 {%0,%1,%2,%3}, [%4];"
        : "=r"(a[0]), "=r"(a[1]), "=r"(a[2]), "=r"(a[3]) : "r"(addr));
}
__device__ __forceinline__ void ldmx2(uint32_t a[2], uint32_t addr) {
    asm volatile("ldmatrix.sync.aligned.m8n8.x2.shared.b16 {%0,%1}, [%2];"
        : "=r"(a[0]), "=r"(a[1]) : "r"(addr));
}
__device__ __forceinline__ void ldmx4t(uint32_t a[4], uint32_t addr) {
    asm volatile("ldmatrix.sync.aligned.m8n8.x4.trans.shared.b16 {%0,%1,%2,%3}, [%4];"
        : "=r"(a[0]), "=r"(a[1]), "=r"(a[2]), "=r"(a[3]) : "r"(addr));
}
__device__ __forceinline__ void mma16816(float c[4], const uint32_t a[4], const uint32_t b[2]) {
    asm volatile("mma.sync.aligned.m16n8k16.row.col.f32.bf16.bf16.f32 "
        "{%0,%1,%2,%3}, {%4,%5,%6,%7}, {%8,%9}, {%0,%1,%2,%3};"
        : "+f"(c[0]), "+f"(c[1]), "+f"(c[2]), "+f"(c[3])
        : "r"(a[0]), "r"(a[1]), "r"(a[2]), "r"(a[3]), "r"(b[0]), "r"(b[1]));
}
#define CP16(dst, src) \
    asm volatile("cp.async.cg.shared.global [%0], [%1], 16;" :: "r"(dst), "l"(src) : "memory")
#define CP_COMMIT() asm volatile("cp.async.commit_group;" ::: "memory")
#define CP_WAIT(n)  asm volatile("cp.async.wait_group %0;" :: "n"(n) : "memory")

// ===================== prep: split kernels ==================================
__global__ __launch_bounds__(256)
void split_concat(const float* __restrict__ mem, const float* __restrict__ inp,
                  __nv_bfloat16* __restrict__ hi, __nv_bfloat16* __restrict__ lo)
{
    size_t idx = ((size_t)blockIdx.x * 256 + threadIdx.x) * 4;
    size_t row = idx >> 10;
    int col = (int)(idx & 1023);
    int b = (int)(row >> 11);
    int k = (int)(row & 2047);
    const float* src = (k < ML) ? mem + ((size_t)(b * ML + k) << 10)
                                : inp + ((size_t)(b * QL + (k - ML)) << 10);
    float4 v = *(const float4*)(src + col);
    __nv_bfloat16 h0, h1, h2, h3, l0, l1, l2, l3;
    split1(v.x, h0, l0); split1(v.y, h1, l1);
    split1(v.z, h2, l2); split1(v.w, h3, l3);
    __nv_bfloat162* H = (__nv_bfloat162*)(hi + idx);
    __nv_bfloat162* L = (__nv_bfloat162*)(lo + idx);
    H[0] = make_bfloat162(h0, h1); H[1] = make_bfloat162(h2, h3);
    L[0] = make_bfloat162(l0, l1); L[1] = make_bfloat162(l2, l3);
}

__global__ __launch_bounds__(256)
void split_plain(const float* __restrict__ src,
                 __nv_bfloat16* __restrict__ hi, __nv_bfloat16* __restrict__ lo)
{
    size_t idx = ((size_t)blockIdx.x * 256 + threadIdx.x) * 4;
    float4 v = *(const float4*)(src + idx);
    __nv_bfloat16 h0, h1, h2, h3, l0, l1, l2, l3;
    split1(v.x, h0, l0); split1(v.y, h1, l1);
    split1(v.z, h2, l2); split1(v.w, h3, l3);
    __nv_bfloat162* H = (__nv_bfloat162*)(hi + idx);
    __nv_bfloat162* L = (__nv_bfloat162*)(lo + idx);
    H[0] = make_bfloat162(h0, h1); H[1] = make_bfloat162(h2, h3);
    L[0] = make_bfloat162(l0, l1); L[1] = make_bfloat162(l2, l3);
}

__global__ __launch_bounds__(256)
void split_transpose(const float* __restrict__ in,
                     __nv_bfloat16* __restrict__ hi, __nv_bfloat16* __restrict__ lo, int N)
{
    __shared__ float s[32][33];
    const int nx = blockIdx.x * 32;
    const int ky = blockIdx.y * 32;
    const int tx = threadIdx.x & 31;
    const int ty = threadIdx.x >> 5;
#pragma unroll
    for (int r = 0; r < 32; r += 8)
        s[ty + r][tx] = in[(size_t)(ky + ty + r) * N + nx + tx];
    __syncthreads();
#pragma unroll
    for (int r = 0; r < 32; r += 8) {
        float x = s[tx][ty + r];
        __nv_bfloat16 h, l;
        split1(x, h, l);
        size_t o = (size_t)(nx + ty + r) * DM + ky + tx;
        hi[o] = h;
        lo[o] = l;
    }
}

// ============== dense GEMM: mma.sync bf16 3-term split (R8 config) ==========
// MODE 0: fp32 C out.  MODE 1: qkv epilogue -> per-head operands.  MODE 2: rr.
#define RS 80
#define ARRB (128 * RS)
#define STGB (4 * ARRB)
#define NSTG 4
#define GEMM_SMEM (NSTG * STGB)

template<int MODE>
__device__ __forceinline__ void store_opnd(int m, int n, float x0, float x1,
                                           const float* __restrict__ u,
                                           const float* __restrict__ v)
{
    int b = m >> 11, tok = m & 2047;
    __nv_bfloat16 h0, l0, h1, l1;
    if (MODE == 2) {
        int h = n >> 6, d = n & 63;
        size_t o = ((size_t)(b * NH + h) * KL + tok) * DH + d;
        split1(x0, h0, l0); split1(x1, h1, l1);
        *(uint32_t*)(g_rrh + o) = pack2(h0, h1);
        *(uint32_t*)(g_rrl + o) = pack2(l0, l1);
    } else if (n < 1024) {
        int h = n >> 6, d = n & 63, i = tok - ML;
        size_t o = ((size_t)(b * NH + h) * QL + i) * DH + d;
        split1(x0 + u[n], h0, l0); split1(x1 + u[n + 1], h1, l1);
        *(uint32_t*)(g_quh + o) = pack2(h0, h1);
        *(uint32_t*)(g_qul + o) = pack2(l0, l1);
        split1(x0 + v[n], h0, l0); split1(x1 + v[n + 1], h1, l1);
        *(uint32_t*)(g_qvh + o) = pack2(h0, h1);
        *(uint32_t*)(g_qvl + o) = pack2(l0, l1);
    } else if (n < 2048) {
        int h = (n - 1024) >> 6, d = n & 63;
        size_t o = ((size_t)(b * NH + h) * KL + tok) * DH + d;
        split1(x0, h0, l0); split1(x1, h1, l1);
        *(uint32_t*)(g_vjh + o) = pack2(h0, h1);
        *(uint32_t*)(g_vjl + o) = pack2(l0, l1);
    } else {
        int h = (n - 2048) >> 6, d = n & 63;
        size_t o = ((size_t)(b * NH + h) * KL + tok) * DH + d;
        split1(x0, h0, l0); split1(x1, h1, l1);
        *(uint32_t*)(g_khh + o) = pack2(h0, h1);
        *(uint32_t*)(g_khl + o) = pack2(l0, l1);
    }
}

template<int MODE>
__global__ __launch_bounds__(256, 1)
void gemm_bf3(const __nv_bfloat16* __restrict__ Ah, const __nv_bfloat16* __restrict__ Al,
              const __nv_bfloat16* __restrict__ Bh, const __nv_bfloat16* __restrict__ Bl,
              const float* __restrict__ bias, float* __restrict__ C, int N,
              const float* __restrict__ u, const float* __restrict__ v)
{
    extern __shared__ char sm[];
    const uint32_t sb = smem_u32(sm);
    const int t = threadIdx.x;
    const int lane = t & 31;
    const int wid = t >> 5;
    const int m0 = blockIdx.y * 128;
    const int n0 = blockIdx.x * 128;
    if (MODE == 1 && n0 < 1024 && ((m0 & 2047) + 128) <= ML) return;

    const int warp_m = (wid & 1) * 64;
    const int warp_n = (wid >> 1) * 32;

    const __nv_bfloat16* srcs[4] = {
        Ah + (size_t)m0 * DM, Al + (size_t)m0 * DM,
        Bh + (size_t)n0 * DM, Bl + (size_t)n0 * DM
    };

    auto issue_stage = [&](int c) {
        uint32_t dst0 = sb + (uint32_t)(c & 3) * STGB;
#pragma unroll
        for (int arr = 0; arr < 4; ++arr) {
#pragma unroll
            for (int rep = 0; rep < 2; ++rep) {
                int ci = t + rep * 256;
                int row = ci >> 2;
                int kc = ci & 3;
                uint32_t dst = dst0 + arr * ARRB + row * RS + kc * 16;
                const __nv_bfloat16* src = srcs[arr] + (size_t)row * DM + c * 32 + kc * 8;
                CP16(dst, src);
            }
        }
    };

    float acc[4][4][4];
#pragma unroll
    for (int im = 0; im < 4; ++im)
#pragma unroll
        for (int jn = 0; jn < 4; ++jn)
#pragma unroll
            for (int q = 0; q < 4; ++q) acc[im][jn][q] = 0.f;

#pragma unroll
    for (int s = 0; s < NSTG - 1; ++s) { issue_stage(s); CP_COMMIT(); }

    const int NCH = DM / 32;
    for (int c = 0; c < NCH; ++c) {
        CP_WAIT(2);
        __syncthreads();
        if (c + 3 < NCH) issue_stage(c + 3);
        CP_COMMIT();

        const uint32_t st = sb + (uint32_t)(c & 3) * STGB;
        const int mrow = lane & 15;
        const int khalf = lane >> 4;
        const int nrow = lane & 7;
        const int khalfb = (lane >> 3) & 1;
#pragma unroll
        for (int kk = 0; kk < 32; kk += 16) {
            uint32_t ah[4][4], al[4][4], bh[4][2], bl[4][2];
#pragma unroll
            for (int im = 0; im < 4; ++im) {
                uint32_t aaddr = st + (warp_m + im * 16 + mrow) * RS + (kk + khalf * 8) * 2;
                ldmx4(ah[im], aaddr);
                ldmx4(al[im], aaddr + ARRB);
            }
#pragma unroll
            for (int jn = 0; jn < 4; ++jn) {
                uint32_t baddr = st + 2 * ARRB + (warp_n + jn * 8 + nrow) * RS + (kk + khalfb * 8) * 2;
                ldmx2(bh[jn], baddr);
                ldmx2(bl[jn], baddr + ARRB);
            }
#pragma unroll
            for (int im = 0; im < 4; ++im)
#pragma unroll
                for (int jn = 0; jn < 4; ++jn) {
                    mma16816(acc[im][jn], ah[im], bh[jn]);
                    mma16816(acc[im][jn], ah[im], bl[jn]);
                    mma16816(acc[im][jn], al[im], bh[jn]);
                }
        }
    }

    if (MODE == 0) {
#pragma unroll
        for (int im = 0; im < 4; ++im) {
            int m = m0 + warp_m + im * 16 + (lane >> 2);
#pragma unroll
            for (int jn = 0; jn < 4; ++jn) {
                int n = n0 + warp_n + jn * 8 + (lane & 3) * 2;
                float b0 = bias[n], b1 = bias[n + 1];
                float2 v0, v1;
                v0.x = acc[im][jn][0] + b0; v0.y = acc[im][jn][1] + b1;
                v1.x = acc[im][jn][2] + b0; v1.y = acc[im][jn][3] + b1;
                *(float2*)(C + (size_t)m * N + n) = v0;
                *(float2*)(C + (size_t)(m + 8) * N + n) = v1;
            }
        }
    } else {
#pragma unroll
        for (int im = 0; im < 4; ++im) {
            int m = m0 + warp_m + im * 16 + (lane >> 2);
#pragma unroll
            for (int jn = 0; jn < 4; ++jn) {
                int n = n0 + warp_n + jn * 8 + (lane & 3) * 2;
                float b0 = bias[n], b1 = bias[n + 1];
                store_opnd<MODE>(m, n, acc[im][jn][0] + b0, acc[im][jn][1] + b1, u, v);
                store_opnd<MODE>(m + 8, n, acc[im][jn][2] + b0, acc[im][jn][3] + b1, u, v);
            }
        }
    }
}

// ============== BD score GEMM (mma, K=64, x4 pair B loads) ==================
#define SRS 144
#define SARRB (128 * SRS)
#define SCORE_SMEM (4 * SARRB)

__global__ __launch_bounds__(256, 1)
void bd_mma()
{
    const int bh = blockIdx.z;
    const int i0 = blockIdx.y * 128;
    const int p0 = blockIdx.x * 128;
    if (i0 + p0 + 254 < QL - 1) return;

    extern __shared__ char sm[];
    const uint32_t sb = smem_u32(sm);
    const int t = threadIdx.x;
    const int lane = t & 31;
    const int wid = t >> 5;
    const int warp_m = (wid & 1) * 64;
    const int warp_n = (wid >> 1) * 32;

    const __nv_bfloat16* srcs[4] = {
        g_qvh + ((size_t)bh * QL + i0) * DH,
        g_qvl + ((size_t)bh * QL + i0) * DH,
        g_rrh + ((size_t)bh * KL + p0) * DH,
        g_rrl + ((size_t)bh * KL + p0) * DH
    };
#pragma unroll
    for (int arr = 0; arr < 4; ++arr) {
#pragma unroll
        for (int rep = 0; rep < 4; ++rep) {
            int ci = t + rep * 256;
            int row = ci >> 3;
            int kc = ci & 7;
            uint32_t dst = sb + arr * SARRB + row * SRS + kc * 16;
            CP16(dst, srcs[arr] + (size_t)row * DH + kc * 8);
        }
    }
    CP_COMMIT();
    CP_WAIT(0);
    __syncthreads();

    float acc[4][4][4];
#pragma unroll
    for (int im = 0; im < 4; ++im)
#pragma unroll
        for (int jn = 0; jn < 4; ++jn)
#pragma unroll
            for (int q = 0; q < 4; ++q) acc[im][jn][q] = 0.f;

    const int mrow = lane & 15;
    const int khalf = lane >> 4;
    const int brow = lane & 7;
    const int bkh = (lane >> 3) & 1;
    const int bpair = lane >> 4;
#pragma unroll
    for (int kk = 0; kk < 64; kk += 16) {
        uint32_t ah[4][4], al[4][4];
#pragma unroll
        for (int im = 0; im < 4; ++im) {
            uint32_t aaddr = sb + (warp_m + im * 16 + mrow) * SRS + (kk + khalf * 8) * 2;
            ldmx4(ah[im], aaddr);
            ldmx4(al[im], aaddr + SARRB);
        }
#pragma unroll
        for (int j2 = 0; j2 < 2; ++j2) {
            uint32_t baddr = sb + 2 * SARRB
                + (warp_n + (j2 * 2 + bpair) * 8 + brow) * SRS + (kk + bkh * 8) * 2;
            uint32_t b4h[4], b4l[4];
            ldmx4(b4h, baddr);
            ldmx4(b4l, baddr + SARRB);
#pragma unroll
            for (int im = 0; im < 4; ++im) {
                mma16816(acc[im][2 * j2],     ah[im], &b4h[0]);
                mma16816(acc[im][2 * j2],     ah[im], &b4l[0]);
                mma16816(acc[im][2 * j2],     al[im], &b4h[0]);
                mma16816(acc[im][2 * j2 + 1], ah[im], &b4h[2]);
                mma16816(acc[im][2 * j2 + 1], ah[im], &b4l[2]);
                mma16816(acc[im][2 * j2 + 1], al[im], &b4h[2]);
            }
        }
    }

#pragma unroll
    for (int im = 0; im < 4; ++im) {
        int m = i0 + warp_m + im * 16 + (lane >> 2);
        float* r0 = g_bd + ((size_t)bh * QL + m) * KL;
        float* r1 = g_bd + ((size_t)bh * QL + m + 8) * KL;
        int sh0 = m - (QL - 1);
        int sh1 = m + 8 - (QL - 1);
#pragma unroll
        for (int jn = 0; jn < 4; ++jn) {
            int p = p0 + warp_n + jn * 8 + (lane & 3) * 2;
            int j0a = p + sh0;
            int j1a = p + sh1;
            if (j0a >= 0)     r0[j0a]     = acc[im][jn][0];
            if (j0a + 1 >= 0) r0[j0a + 1] = acc[im][jn][1];
            if (j1a >= 0)     r1[j1a]     = acc[im][jn][2];
            if (j1a + 1 >= 0) r1[j1a + 1] = acc[im][jn][3];
        }
    }
}

// ========== warp-autonomous flash attention (x4 pair loads) ================
#define FCH 128
#define AQ_OFF 0u
#define AK_OFF 36864u
#define AV_OFF 110592u
#define ABUF 36864u
#define ATTN_SMEM 184320

__global__ __launch_bounds__(256, 1)
void attn_flash()
{
    extern __shared__ char sm[];
    const uint32_t sb = smem_u32(sm);
    const int bh = blockIdx.y;
    const int b = bh >> 4, h = bh & 15;
    const int i0 = (gridDim.x - 1 - blockIdx.x) * 128;
    const int t = threadIdx.x, lane = t & 31, wid = t >> 5;
    const int warp_m = wid * 16;

    const __nv_bfloat16* Kh  = g_khh + (size_t)bh * KL * DH;
    const __nv_bfloat16* Klo = g_khl + (size_t)bh * KL * DH;
    const __nv_bfloat16* Vjh = g_vjh + (size_t)bh * KL * DH;
    const __nv_bfloat16* Vjl = g_vjl + (size_t)bh * KL * DH;

    {
        const __nv_bfloat16* Qh = g_quh + ((size_t)bh * QL + i0) * DH;
        const __nv_bfloat16* Ql = g_qul + ((size_t)bh * QL + i0) * DH;
#pragma unroll
        for (int rep = 0; rep < 4; ++rep) {
            int ci = t + rep * 256;
            int row = ci >> 3, kc = ci & 7;
            uint32_t dst = sb + AQ_OFF + row * SRS + kc * 16;
            CP16(dst, Qh + (size_t)row * DH + kc * 8);
            CP16(dst + 18432u, Ql + (size_t)row * DH + kc * 8);
        }
    }
    CP_COMMIT();

    auto loadKV = [&](int c) {
        uint32_t kd = sb + AK_OFF + (uint32_t)(c & 1) * ABUF;
        uint32_t vd = sb + AV_OFF + (uint32_t)(c & 1) * ABUF;
#pragma unroll
        for (int rep = 0; rep < 4; ++rep) {
            int ci = t + rep * 256;
            int row = ci >> 3, kc = ci & 7;
            uint32_t o = row * SRS + kc * 16;
            CP16(kd + o, Kh + (size_t)(c * FCH + row) * DH + kc * 8);
            CP16(kd + o + 18432u, Klo + (size_t)(c * FCH + row) * DH + kc * 8);
            CP16(vd + o, Vjh + (size_t)(c * FCH + row) * DH + kc * 8);
            CP16(vd + o + 18432u, Vjl + (size_t)(c * FCH + row) * DH + kc * 8);
        }
    };

    const int nch = (ML + i0 + 128) / FCH;
    loadKV(0); CP_COMMIT();
    loadKV(1); CP_COMMIT();

    const int mrow = lane & 15, khalf = lane >> 4;
    const int brow = lane & 7, bkh = (lane >> 3) & 1, bpair = lane >> 4;
    const int lane16 = lane & 15;
    uint32_t aqh[4][4], aql[4][4];
    CP_WAIT(2);
    __syncthreads();
#pragma unroll
    for (int kf = 0; kf < 4; ++kf) {
        uint32_t aaddr = sb + AQ_OFF + (warp_m + mrow) * SRS + (kf * 16 + khalf * 8) * 2;
        ldmx4(aqh[kf], aaddr);
        ldmx4(aql[kf], aaddr + 18432u);
    }

    const int r0 = lane >> 2;
    const int colb = (lane & 3) * 2;
    const float* bdr0 = g_bd + ((size_t)bh * QL + i0 + warp_m + r0) * KL;
    const float* bdr1 = bdr0 + (size_t)8 * KL;
    const int lim0 = ML + i0 + warp_m + r0;
    const int lim1 = lim0 + 8;

    float pvacc[8][4];
#pragma unroll
    for (int nf = 0; nf < 8; ++nf)
#pragma unroll
        for (int q = 0; q < 4; ++q) pvacc[nf][q] = 0.f;
    float ssum0 = 0.f, ssum1 = 0.f;
    float mold0 = -1e30f, mold1 = -1e30f;

    for (int c = 0; c < nch; ++c) {
        CP_WAIT(1);
        __syncthreads();
        const uint32_t kst = sb + AK_OFF + (uint32_t)(c & 1) * ABUF;
        const uint32_t vst = sb + AV_OFF + (uint32_t)(c & 1) * ABUF;
        const int j0 = c * FCH;

        // ---- S = (q+u) . K^T  (x4 pair loads of K fragments) ----
        float S[16][4];
#pragma unroll
        for (int nf2 = 0; nf2 < 8; ++nf2) {
            S[2 * nf2][0] = S[2 * nf2][1] = S[2 * nf2][2] = S[2 * nf2][3] = 0.f;
            S[2 * nf2 + 1][0] = S[2 * nf2 + 1][1] = S[2 * nf2 + 1][2] = S[2 * nf2 + 1][3] = 0.f;
#pragma unroll
            for (int kf = 0; kf < 4; ++kf) {
                uint32_t baddr = kst + ((nf2 * 2 + bpair) * 8 + brow) * SRS
                               + (kf * 16 + bkh * 8) * 2;
                uint32_t b4h[4], b4l[4];
                ldmx4(b4h, baddr);
                ldmx4(b4l, baddr + 18432u);
                mma16816(S[2 * nf2],     aqh[kf], &b4h[0]);
                mma16816(S[2 * nf2],     aqh[kf], &b4l[0]);
                mma16816(S[2 * nf2],     aql[kf], &b4h[0]);
                mma16816(S[2 * nf2 + 1], aqh[kf], &b4h[2]);
                mma16816(S[2 * nf2 + 1], aqh[kf], &b4l[2]);
                mma16816(S[2 * nf2 + 1], aql[kf], &b4h[2]);
            }
        }

        // ---- + BD, scale, mask, row max ----
        const bool nomask = (j0 + 127) <= lim0;
        float mx0 = -1e30f, mx1 = -1e30f;
#pragma unroll
        for (int nf = 0; nf < 16; ++nf) {
            int jc = j0 + nf * 8 + colb;
            float2 b0 = *(const float2*)(bdr0 + jc);
            float2 b1 = *(const float2*)(bdr1 + jc);
            float s0 = (S[nf][0] + b0.x) * 0.125f;
            float s1 = (S[nf][1] + b0.y) * 0.125f;
            float s2 = (S[nf][2] + b1.x) * 0.125f;
            float s3 = (S[nf][3] + b1.y) * 0.125f;
            if (!nomask) {
                s0 = (jc     <= lim0) ? s0 : -1e30f;
                s1 = (jc + 1 <= lim0) ? s1 : -1e30f;
                s2 = (jc     <= lim1) ? s2 : -1e30f;
                s3 = (jc + 1 <= lim1) ? s3 : -1e30f;
            }
            S[nf][0] = s0; S[nf][1] = s1; S[nf][2] = s2; S[nf][3] = s3;
            mx0 = fmaxf(mx0, fmaxf(s0, s1));
            mx1 = fmaxf(mx1, fmaxf(s2, s3));
        }
        mx0 = fmaxf(mx0, __shfl_xor_sync(0xffffffffu, mx0, 1));
        mx0 = fmaxf(mx0, __shfl_xor_sync(0xffffffffu, mx0, 2));
        mx1 = fmaxf(mx1, __shfl_xor_sync(0xffffffffu, mx1, 1));
        mx1 = fmaxf(mx1, __shfl_xor_sync(0xffffffffu, mx1, 2));
        const float mnew0 = fmaxf(mold0, mx0);
        const float mnew1 = fmaxf(mold1, mx1);
        const float sc0 = __expf(mold0 - mnew0);
        const float sc1 = __expf(mold1 - mnew1);
        mold0 = mnew0; mold1 = mnew1;
        ssum0 *= sc0; ssum1 *= sc1;
#pragma unroll
        for (int nf = 0; nf < 8; ++nf) {
            pvacc[nf][0] *= sc0; pvacc[nf][1] *= sc0;
            pvacc[nf][2] *= sc1; pvacc[nf][3] *= sc1;
        }
#pragma unroll
        for (int nf = 0; nf < 16; ++nf) {
            S[nf][0] = __expf(S[nf][0] - mnew0);
            S[nf][1] = __expf(S[nf][1] - mnew0);
            S[nf][2] = __expf(S[nf][2] - mnew1);
            S[nf][3] = __expf(S[nf][3] - mnew1);
            ssum0 += S[nf][0] + S[nf][1];
            ssum1 += S[nf][2] + S[nf][3];
        }

        // ---- P @ V (x4.trans pair loads of V fragments) ----
#pragma unroll
        for (int kf = 0; kf < 8; ++kf) {
            uint32_t pah[4], pal[4];
            __nv_bfloat16 h0, l0, h1, l1;
            split1(S[2 * kf][0], h0, l0);     split1(S[2 * kf][1], h1, l1);
            pah[0] = pack2(h0, h1);           pal[0] = pack2(l0, l1);
            split1(S[2 * kf][2], h0, l0);     split1(S[2 * kf][3], h1, l1);
            pah[1] = pack2(h0, h1);           pal[1] = pack2(l0, l1);
            split1(S[2 * kf + 1][0], h0, l0); split1(S[2 * kf + 1][1], h1, l1);
            pah[2] = pack2(h0, h1);           pal[2] = pack2(l0, l1);
            split1(S[2 * kf + 1][2], h0, l0); split1(S[2 * kf + 1][3], h1, l1);
            pah[3] = pack2(h0, h1);           pal[3] = pack2(l0, l1);
#pragma unroll
            for (int nf2 = 0; nf2 < 4; ++nf2) {
                uint32_t baddr = vst + (kf * 16 + lane16) * SRS + (nf2 * 2 + bpair) * 16;
                uint32_t b4h[4], b4l[4];
                ldmx4t(b4h, baddr);
                ldmx4t(b4l, baddr + 18432u);
                mma16816(pvacc[2 * nf2],     pah, &b4h[0]);
                mma16816(pvacc[2 * nf2],     pah, &b4l[0]);
                mma16816(pvacc[2 * nf2],     pal, &b4h[0]);
                mma16816(pvacc[2 * nf2 + 1], pah, &b4h[2]);
                mma16816(pvacc[2 * nf2 + 1], pah, &b4l[2]);
                mma16816(pvacc[2 * nf2 + 1], pal, &b4h[2]);
            }
        }

        __syncthreads();
        if (c + 2 < nch) loadKV(c + 2);
        CP_COMMIT();
    }

    // ---- epilogue: normalize, split to bf16 hi/lo, store to g_oh/g_ol ----
    ssum0 += __shfl_xor_sync(0xffffffffu, ssum0, 1);
    ssum0 += __shfl_xor_sync(0xffffffffu, ssum0, 2);
    ssum1 += __shfl_xor_sync(0xffffffffu, ssum1, 1);
    ssum1 += __shfl_xor_sync(0xffffffffu, ssum1, 2);
    const float iv0 = 1.f / ssum0;
    const float iv1 = 1.f / ssum1;
    const size_t orow0 = (size_t)(b * QL + i0 + warp_m + r0) * DM + h * DH;
    const size_t orow1 = orow0 + (size_t)8 * DM;
#pragma unroll
    for (int nf = 0; nf < 8; ++nf) {
        int d = nf * 8 + colb;
        __nv_bfloat16 hh0, ll0, hh1, ll1;
        split1(pvacc[nf][0] * iv0, hh0, ll0);
        split1(pvacc[nf][1] * iv0, hh1, ll1);
        *(uint32_t*)(g_oh + orow0 + d) = pack2(hh0, hh1);
        *(uint32_t*)(g_ol + orow0 + d) = pack2(ll0, ll1);
        split1(pvacc[nf][2] * iv1, hh0, ll0);
        split1(pvacc[nf][3] * iv1, hh1, ll1);
        *(uint32_t*)(g_oh + orow1 + d) = pack2(hh0, hh1);
        *(uint32_t*)(g_ol + orow1 + d) = pack2(ll0, ll1);
    }
}

// =========================== launch =======================================
extern "C" void kernel_launch(void* const* d_in, const int* in_sizes, int n_in,
                              void* d_out, int out_size)
{
    const float* inputs = (const float*)d_in[0];
    const float* mem    = (const float*)d_in[1];
    const float* r      = (const float*)d_in[2];
    const float* W_qkv  = (const float*)d_in[3];
    const float* b_qkv  = (const float*)d_in[4];
    const float* W_r    = (const float*)d_in[5];
    const float* b_r    = (const float*)d_in[6];
    const float* W_o    = (const float*)d_in[7];
    const float* b_o    = (const float*)d_in[8];
    const float* u      = (const float*)d_in[9];
    const float* v      = (const float*)d_in[10];
    float* out = (float*)d_out;

    __nv_bfloat16 *pah, *pal, *prh, *prl, *poh, *pol;
    __nv_bfloat16 *pwqh, *pwql, *pwrh, *pwrl, *pwoh, *pwol;
    cudaGetSymbolAddress((void**)&pah,   g_ah);
    cudaGetSymbolAddress((void**)&pal,   g_al);
    cudaGetSymbolAddress((void**)&prh,   g_rh);
    cudaGetSymbolAddress((void**)&prl,   g_rl);
    cudaGetSymbolAddress((void**)&poh,   g_oh);
    cudaGetSymbolAddress((void**)&pol,   g_ol);
    cudaGetSymbolAddress((void**)&pwqh,  g_wqh);
    cudaGetSymbolAddress((void**)&pwql,  g_wql);
    cudaGetSymbolAddress((void**)&pwrh,  g_wrh);
    cudaGetSymbolAddress((void**)&pwrl,  g_wrl);
    cudaGetSymbolAddress((void**)&pwoh,  g_woh);
    cudaGetSymbolAddress((void**)&pwol,  g_wol);

    cudaFuncSetAttribute(gemm_bf3<0>, cudaFuncAttributeMaxDynamicSharedMemorySize, GEMM_SMEM);
    cudaFuncSetAttribute(gemm_bf3<1>, cudaFuncAttributeMaxDynamicSharedMemorySize, GEMM_SMEM);
    cudaFuncSetAttribute(gemm_bf3<2>, cudaFuncAttributeMaxDynamicSharedMemorySize, GEMM_SMEM);
    cudaFuncSetAttribute(bd_mma, cudaFuncAttributeMaxDynamicSharedMemorySize, SCORE_SMEM);
    cudaFuncSetAttribute(attn_flash, cudaFuncAttributeMaxDynamicSharedMemorySize, ATTN_SMEM);

    dim3 blk(256);

    // --- A-side / weight splits ---
    split_concat<<<4096, blk>>>(mem, inputs, pah, pal);
    split_plain<<<4096, blk>>>(r, prh, prl);
    split_transpose<<<dim3(3072 / 32, 1024 / 32), blk>>>(W_qkv, pwqh, pwql, 3072);
    split_transpose<<<dim3(1024 / 32, 1024 / 32), blk>>>(W_r,   pwrh, pwrl, 1024);
    split_transpose<<<dim3(1024 / 32, 1024 / 32), blk>>>(W_o,   pwoh, pwol, 1024);

    // 1) qkv projection with fused per-head operand epilogue
    gemm_bf3<1><<<dim3(3072 / 128, 4096 / 128), blk, GEMM_SMEM>>>(
        pah, pal, pwqh, pwql, b_qkv, nullptr, 3072, u, v);
    // 2) r projection with fused rr epilogue
    gemm_bf3<2><<<dim3(1024 / 128, 4096 / 128), blk, GEMM_SMEM>>>(
        prh, prl, pwrh, pwrl, b_r, nullptr, 1024, nullptr, nullptr);

    // 3) BD (pre-shifted, fp32) -> g_bd
    bd_mma<<<dim3(KL / 128, QL / 128, BQ * NH), blk, SCORE_SMEM>>>();

    // 4) fused AC + online softmax + P@V -> g_oh/g_ol
    attn_flash<<<dim3(QL / 128, BQ * NH), blk, ATTN_SMEM>>>();

    // 5) final projection -> d_out
    gemm_bf3<0><<<dim3(1024 / 128, 2048 / 128), blk, GEMM_SMEM>>>(
        poh, pol, pwoh, pwol, b_o, out, 1024, nullptr, nullptr);
}

// round 12
// speedup vs baseline: 1.0561x; 1.0067x over previous
#include <cuda_runtime.h>
#include <cuda_bf16.h>
#include <cstdint>
#include <cstddef>

#define BQ 2
#define QL 1024
#define ML 1024
#define KL 2048
#define DM 1024
#define NH 16
#define DH 64

// ---------------- scratch (device globals: allocation-free) ----------------
__device__ float g_bd[(size_t)32 * 1024 * 2048];    // BD (pre-shifted) [B*H, Q, K]

__device__ __nv_bfloat16 g_ah[(size_t)4096 * 1024], g_al[(size_t)4096 * 1024];
__device__ __nv_bfloat16 g_rh[(size_t)4096 * 1024], g_rl[(size_t)4096 * 1024];
__device__ __nv_bfloat16 g_oh[(size_t)2048 * 1024], g_ol[(size_t)2048 * 1024];
__device__ __nv_bfloat16 g_wqh[(size_t)3072 * 1024], g_wql[(size_t)3072 * 1024];
__device__ __nv_bfloat16 g_wrh[(size_t)1024 * 1024], g_wrl[(size_t)1024 * 1024];
__device__ __nv_bfloat16 g_woh[(size_t)1024 * 1024], g_wol[(size_t)1024 * 1024];

__device__ __nv_bfloat16 g_quh[(size_t)32 * 1024 * 64], g_qul[(size_t)32 * 1024 * 64];
__device__ __nv_bfloat16 g_qvh[(size_t)32 * 1024 * 64], g_qvl[(size_t)32 * 1024 * 64];
__device__ __nv_bfloat16 g_khh[(size_t)32 * 2048 * 64], g_khl[(size_t)32 * 2048 * 64];
__device__ __nv_bfloat16 g_rrh[(size_t)32 * 2048 * 64], g_rrl[(size_t)32 * 2048 * 64];
__device__ __nv_bfloat16 g_vjh[(size_t)32 * 2048 * 64], g_vjl[(size_t)32 * 2048 * 64];

// ======================= helpers ===========================================
__device__ __forceinline__ uint32_t smem_u32(const void* p) {
    uint32_t a;
    asm("{ .reg .u64 t; cvta.to.shared.u64 t, %1; cvt.u32.u64 %0, t; }"
        : "=r"(a) : "l"(p));
    return a;
}
__device__ __forceinline__ void split1(float x, __nv_bfloat16& h, __nv_bfloat16& l) {
    h = __float2bfloat16_rn(x);
    l = __float2bfloat16_rn(x - __bfloat162float(h));
}
__device__ __forceinline__ uint32_t pack2(__nv_bfloat16 a, __nv_bfloat16 b) {
    __nv_bfloat162 v = make_bfloat162(a, b);
    return *(uint32_t*)&v;
}
__device__ __forceinline__ void ldmx4(uint32_t a[4], uint32_t addr) {
    asm volatile("ldmatrix.sync.aligned.m8n8.x4.shared.b16 {%0,%1,%2,%3}, [%4];"
        : "=r"(a[0]), "=r"(a[1]), "=r"(a[2]), "=r"(a[3]) : "r"(addr));
}
__device__ __forceinline__ void ldmx4t(uint32_t a[4], uint32_t addr) {
    asm volatile("ldmatrix.sync.aligned.m8n8.x4.trans.shared.b16 {%0,%1,%2,%3}, [%4];"
        : "=r"(a[0]), "=r"(a[1]), "=r"(a[2]), "=r"(a[3]) : "r"(addr));
}
__device__ __forceinline__ void mma16816(float c[4], const uint32_t a[4], const uint32_t b[2]) {
    asm volatile("mma.sync.aligned.m16n8k16.row.col.f32.bf16.bf16.f32 "
        "{%0,%1,%2,%3}, {%4,%5,%6,%7}, {%8,%9}, {%0,%1,%2,%3};"
        : "+f"(c[0]), "+f"(c[1]), "+f"(c[2]), "+f"(c[3])
        : "r"(a[0]), "r"(a[1]), "r"(a[2]), "r"(a[3]), "r"(b[0]), "r"(b[1]));
}
#define CP16(dst, src) \
    asm volatile("cp.async.cg.shared.global [%0], [%1], 16;" :: "r"(dst), "l"(src) : "memory")
#define CP_COMMIT() asm volatile("cp.async.commit_group;" ::: "memory")
#define CP_WAIT(n)  asm volatile("cp.async.wait_group %0;" :: "n"(n) : "memory")

// ===================== prep: split kernels ==================================
__global__ __launch_bounds__(256)
void split_concat(const float* __restrict__ mem, const float* __restrict__ inp,
                  __nv_bfloat16* __restrict__ hi, __nv_bfloat16* __restrict__ lo)
{
    size_t idx = ((size_t)blockIdx.x * 256 + threadIdx.x) * 4;
    size_t row = idx >> 10;
    int col = (int)(idx & 1023);
    int b = (int)(row >> 11);
    int k = (int)(row & 2047);
    const float* src = (k < ML) ? mem + ((size_t)(b * ML + k) << 10)
                                : inp + ((size_t)(b * QL + (k - ML)) << 10);
    float4 v = *(const float4*)(src + col);
    __nv_bfloat16 h0, h1, h2, h3, l0, l1, l2, l3;
    split1(v.x, h0, l0); split1(v.y, h1, l1);
    split1(v.z, h2, l2); split1(v.w, h3, l3);
    __nv_bfloat162* H = (__nv_bfloat162*)(hi + idx);
    __nv_bfloat162* L = (__nv_bfloat162*)(lo + idx);
    H[0] = make_bfloat162(h0, h1); H[1] = make_bfloat162(h2, h3);
    L[0] = make_bfloat162(l0, l1); L[1] = make_bfloat162(l2, l3);
}

__global__ __launch_bounds__(256)
void split_plain(const float* __restrict__ src,
                 __nv_bfloat16* __restrict__ hi, __nv_bfloat16* __restrict__ lo)
{
    size_t idx = ((size_t)blockIdx.x * 256 + threadIdx.x) * 4;
    float4 v = *(const float4*)(src + idx);
    __nv_bfloat16 h0, h1, h2, h3, l0, l1, l2, l3;
    split1(v.x, h0, l0); split1(v.y, h1, l1);
    split1(v.z, h2, l2); split1(v.w, h3, l3);
    __nv_bfloat162* H = (__nv_bfloat162*)(hi + idx);
    __nv_bfloat162* L = (__nv_bfloat162*)(lo + idx);
    H[0] = make_bfloat162(h0, h1); H[1] = make_bfloat162(h2, h3);
    L[0] = make_bfloat162(l0, l1); L[1] = make_bfloat162(l2, l3);
}

__global__ __launch_bounds__(256)
void split_transpose(const float* __restrict__ in,
                     __nv_bfloat16* __restrict__ hi, __nv_bfloat16* __restrict__ lo, int N)
{
    __shared__ float s[32][33];
    const int nx = blockIdx.x * 32;
    const int ky = blockIdx.y * 32;
    const int tx = threadIdx.x & 31;
    const int ty = threadIdx.x >> 5;
#pragma unroll
    for (int r = 0; r < 32; r += 8)
        s[ty + r][tx] = in[(size_t)(ky + ty + r) * N + nx + tx];
    __syncthreads();
#pragma unroll
    for (int r = 0; r < 32; r += 8) {
        float x = s[tx][ty + r];
        __nv_bfloat16 h, l;
        split1(x, h, l);
        size_t o = (size_t)(nx + ty + r) * DM + ky + tx;
        hi[o] = h;
        lo[o] = l;
    }
}

// ============== dense GEMM: mma.sync bf16 3-term split ======================
// R11 config (128x128, 4-stage) + x4 pair B-fragment loads.
#define RS 80
#define ARRB (128 * RS)
#define STGB (4 * ARRB)
#define NSTG 4
#define GEMM_SMEM (NSTG * STGB)

template<int MODE>
__device__ __forceinline__ void store_opnd(int m, int n, float x0, float x1,
                                           const float* __restrict__ u,
                                           const float* __restrict__ v)
{
    int b = m >> 11, tok = m & 2047;
    __nv_bfloat16 h0, l0, h1, l1;
    if (MODE == 2) {
        int h = n >> 6, d = n & 63;
        size_t o = ((size_t)(b * NH + h) * KL + tok) * DH + d;
        split1(x0, h0, l0); split1(x1, h1, l1);
        *(uint32_t*)(g_rrh + o) = pack2(h0, h1);
        *(uint32_t*)(g_rrl + o) = pack2(l0, l1);
    } else if (n < 1024) {
        int h = n >> 6, d = n & 63, i = tok - ML;
        size_t o = ((size_t)(b * NH + h) * QL + i) * DH + d;
        split1(x0 + u[n], h0, l0); split1(x1 + u[n + 1], h1, l1);
        *(uint32_t*)(g_quh + o) = pack2(h0, h1);
        *(uint32_t*)(g_qul + o) = pack2(l0, l1);
        split1(x0 + v[n], h0, l0); split1(x1 + v[n + 1], h1, l1);
        *(uint32_t*)(g_qvh + o) = pack2(h0, h1);
        *(uint32_t*)(g_qvl + o) = pack2(l0, l1);
    } else if (n < 2048) {
        int h = (n - 1024) >> 6, d = n & 63;
        size_t o = ((size_t)(b * NH + h) * KL + tok) * DH + d;
        split1(x0, h0, l0); split1(x1, h1, l1);
        *(uint32_t*)(g_vjh + o) = pack2(h0, h1);
        *(uint32_t*)(g_vjl + o) = pack2(l0, l1);
    } else {
        int h = (n - 2048) >> 6, d = n & 63;
        size_t o = ((size_t)(b * NH + h) * KL + tok) * DH + d;
        split1(x0, h0, l0); split1(x1, h1, l1);
        *(uint32_t*)(g_khh + o) = pack2(h0, h1);
        *(uint32_t*)(g_khl + o) = pack2(l0, l1);
    }
}

template<int MODE>
__global__ __launch_bounds__(256, 1)
void gemm_bf3(const __nv_bfloat16* __restrict__ Ah, const __nv_bfloat16* __restrict__ Al,
              const __nv_bfloat16* __restrict__ Bh, const __nv_bfloat16* __restrict__ Bl,
              const float* __restrict__ bias, float* __restrict__ C, int N,
              const float* __restrict__ u, const float* __restrict__ v)
{
    extern __shared__ char sm[];
    const uint32_t sb = smem_u32(sm);
    const int t = threadIdx.x;
    const int lane = t & 31;
    const int wid = t >> 5;
    const int m0 = blockIdx.y * 128;
    const int n0 = blockIdx.x * 128;
    if (MODE == 1 && n0 < 1024 && ((m0 & 2047) + 128) <= ML) return;

    const int warp_m = (wid & 1) * 64;
    const int warp_n = (wid >> 1) * 32;

    const __nv_bfloat16* srcs[4] = {
        Ah + (size_t)m0 * DM, Al + (size_t)m0 * DM,
        Bh + (size_t)n0 * DM, Bl + (size_t)n0 * DM
    };

    auto issue_stage = [&](int c) {
        uint32_t dst0 = sb + (uint32_t)(c & 3) * STGB;
#pragma unroll
        for (int arr = 0; arr < 4; ++arr) {
#pragma unroll
            for (int rep = 0; rep < 2; ++rep) {
                int ci = t + rep * 256;
                int row = ci >> 2;
                int kc = ci & 3;
                uint32_t dst = dst0 + arr * ARRB + row * RS + kc * 16;
                const __nv_bfloat16* src = srcs[arr] + (size_t)row * DM + c * 32 + kc * 8;
                CP16(dst, src);
            }
        }
    };

    float acc[4][4][4];
#pragma unroll
    for (int im = 0; im < 4; ++im)
#pragma unroll
        for (int jn = 0; jn < 4; ++jn)
#pragma unroll
            for (int q = 0; q < 4; ++q) acc[im][jn][q] = 0.f;

#pragma unroll
    for (int s = 0; s < NSTG - 1; ++s) { issue_stage(s); CP_COMMIT(); }

    const int mrow = lane & 15;
    const int khalf = lane >> 4;
    const int brow = lane & 7;
    const int bkh = (lane >> 3) & 1;
    const int bpair = lane >> 4;

    const int NCH = DM / 32;
    for (int c = 0; c < NCH; ++c) {
        CP_WAIT(2);
        __syncthreads();
        if (c + 3 < NCH) issue_stage(c + 3);
        CP_COMMIT();

        const uint32_t st = sb + (uint32_t)(c & 3) * STGB;
#pragma unroll
        for (int kk = 0; kk < 32; kk += 16) {
            uint32_t ah[4][4], al[4][4];
#pragma unroll
            for (int im = 0; im < 4; ++im) {
                uint32_t aaddr = st + (warp_m + im * 16 + mrow) * RS + (kk + khalf * 8) * 2;
                ldmx4(ah[im], aaddr);
                ldmx4(al[im], aaddr + ARRB);
            }
#pragma unroll
            for (int j2 = 0; j2 < 2; ++j2) {
                uint32_t baddr = st + 2 * ARRB
                    + (warp_n + (j2 * 2 + bpair) * 8 + brow) * RS + (kk + bkh * 8) * 2;
                uint32_t b4h[4], b4l[4];
                ldmx4(b4h, baddr);
                ldmx4(b4l, baddr + ARRB);
#pragma unroll
                for (int im = 0; im < 4; ++im) {
                    mma16816(acc[im][2 * j2],     ah[im], &b4h[0]);
                    mma16816(acc[im][2 * j2],     ah[im], &b4l[0]);
                    mma16816(acc[im][2 * j2],     al[im], &b4h[0]);
                    mma16816(acc[im][2 * j2 + 1], ah[im], &b4h[2]);
                    mma16816(acc[im][2 * j2 + 1], ah[im], &b4l[2]);
                    mma16816(acc[im][2 * j2 + 1], al[im], &b4h[2]);
                }
            }
        }
    }

    if (MODE == 0) {
#pragma unroll
        for (int im = 0; im < 4; ++im) {
            int m = m0 + warp_m + im * 16 + (lane >> 2);
#pragma unroll
            for (int jn = 0; jn < 4; ++jn) {
                int n = n0 + warp_n + jn * 8 + (lane & 3) * 2;
                float b0 = bias[n], b1 = bias[n + 1];
                float2 v0, v1;
                v0.x = acc[im][jn][0] + b0; v0.y = acc[im][jn][1] + b1;
                v1.x = acc[im][jn][2] + b0; v1.y = acc[im][jn][3] + b1;
                *(float2*)(C + (size_t)m * N + n) = v0;
                *(float2*)(C + (size_t)(m + 8) * N + n) = v1;
            }
        }
    } else {
#pragma unroll
        for (int im = 0; im < 4; ++im) {
            int m = m0 + warp_m + im * 16 + (lane >> 2);
#pragma unroll
            for (int jn = 0; jn < 4; ++jn) {
                int n = n0 + warp_n + jn * 8 + (lane & 3) * 2;
                float b0 = bias[n], b1 = bias[n + 1];
                store_opnd<MODE>(m, n, acc[im][jn][0] + b0, acc[im][jn][1] + b1, u, v);
                store_opnd<MODE>(m + 8, n, acc[im][jn][2] + b0, acc[im][jn][3] + b1, u, v);
            }
        }
    }
}

// ============== BD score GEMM (mma, K=64, x4 pair B loads) ==================
#define SRS 144
#define SARRB (128 * SRS)
#define SCORE_SMEM (4 * SARRB)

__global__ __launch_bounds__(256, 1)
void bd_mma()
{
    const int bh = blockIdx.z;
    const int i0 = blockIdx.y * 128;
    const int p0 = blockIdx.x * 128;
    if (i0 + p0 + 254 < QL - 1) return;

    extern __shared__ char sm[];
    const uint32_t sb = smem_u32(sm);
    const int t = threadIdx.x;
    const int lane = t & 31;
    const int wid = t >> 5;
    const int warp_m = (wid & 1) * 64;
    const int warp_n = (wid >> 1) * 32;

    const __nv_bfloat16* srcs[4] = {
        g_qvh + ((size_t)bh * QL + i0) * DH,
        g_qvl + ((size_t)bh * QL + i0) * DH,
        g_rrh + ((size_t)bh * KL + p0) * DH,
        g_rrl + ((size_t)bh * KL + p0) * DH
    };
#pragma unroll
    for (int arr = 0; arr < 4; ++arr) {
#pragma unroll
        for (int rep = 0; rep < 4; ++rep) {
            int ci = t + rep * 256;
            int row = ci >> 3;
            int kc = ci & 7;
            uint32_t dst = sb + arr * SARRB + row * SRS + kc * 16;
            CP16(dst, srcs[arr] + (size_t)row * DH + kc * 8);
        }
    }
    CP_COMMIT();
    CP_WAIT(0);
    __syncthreads();

    float acc[4][4][4];
#pragma unroll
    for (int im = 0; im < 4; ++im)
#pragma unroll
        for (int jn = 0; jn < 4; ++jn)
#pragma unroll
            for (int q = 0; q < 4; ++q) acc[im][jn][q] = 0.f;

    const int mrow = lane & 15;
    const int khalf = lane >> 4;
    const int brow = lane & 7;
    const int bkh = (lane >> 3) & 1;
    const int bpair = lane >> 4;
#pragma unroll
    for (int kk = 0; kk < 64; kk += 16) {
        uint32_t ah[4][4], al[4][4];
#pragma unroll
        for (int im = 0; im < 4; ++im) {
            uint32_t aaddr = sb + (warp_m + im * 16 + mrow) * SRS + (kk + khalf * 8) * 2;
            ldmx4(ah[im], aaddr);
            ldmx4(al[im], aaddr + SARRB);
        }
#pragma unroll
        for (int j2 = 0; j2 < 2; ++j2) {
            uint32_t baddr = sb + 2 * SARRB
                + (warp_n + (j2 * 2 + bpair) * 8 + brow) * SRS + (kk + bkh * 8) * 2;
            uint32_t b4h[4], b4l[4];
            ldmx4(b4h, baddr);
            ldmx4(b4l, baddr + SARRB);
#pragma unroll
            for (int im = 0; im < 4; ++im) {
                mma16816(acc[im][2 * j2],     ah[im], &b4h[0]);
                mma16816(acc[im][2 * j2],     ah[im], &b4l[0]);
                mma16816(acc[im][2 * j2],     al[im], &b4h[0]);
                mma16816(acc[im][2 * j2 + 1], ah[im], &b4h[2]);
                mma16816(acc[im][2 * j2 + 1], ah[im], &b4l[2]);
                mma16816(acc[im][2 * j2 + 1], al[im], &b4h[2]);
            }
        }
    }

#pragma unroll
    for (int im = 0; im < 4; ++im) {
        int m = i0 + warp_m + im * 16 + (lane >> 2);
        float* r0 = g_bd + ((size_t)bh * QL + m) * KL;
        float* r1 = g_bd + ((size_t)bh * QL + m + 8) * KL;
        int sh0 = m - (QL - 1);
        int sh1 = m + 8 - (QL - 1);
#pragma unroll
        for (int jn = 0; jn < 4; ++jn) {
            int p = p0 + warp_n + jn * 8 + (lane & 3) * 2;
            int j0a = p + sh0;
            int j1a = p + sh1;
            if (j0a >= 0)     r0[j0a]     = acc[im][jn][0];
            if (j0a + 1 >= 0) r0[j0a + 1] = acc[im][jn][1];
            if (j1a >= 0)     r1[j1a]     = acc[im][jn][2];
            if (j1a + 1 >= 0) r1[j1a + 1] = acc[im][jn][3];
        }
    }
}

// ========== warp-autonomous flash attention (x4 pair loads) ================
#define FCH 128
#define AQ_OFF 0u
#define AK_OFF 36864u
#define AV_OFF 110592u
#define ABUF 36864u
#define ATTN_SMEM 184320

__global__ __launch_bounds__(256, 1)
void attn_flash()
{
    extern __shared__ char sm[];
    const uint32_t sb = smem_u32(sm);
    const int bh = blockIdx.y;
    const int b = bh >> 4, h = bh & 15;
    const int i0 = (gridDim.x - 1 - blockIdx.x) * 128;
    const int t = threadIdx.x, lane = t & 31, wid = t >> 5;
    const int warp_m = wid * 16;

    const __nv_bfloat16* Kh  = g_khh + (size_t)bh * KL * DH;
    const __nv_bfloat16* Klo = g_khl + (size_t)bh * KL * DH;
    const __nv_bfloat16* Vjh = g_vjh + (size_t)bh * KL * DH;
    const __nv_bfloat16* Vjl = g_vjl + (size_t)bh * KL * DH;

    {
        const __nv_bfloat16* Qh = g_quh + ((size_t)bh * QL + i0) * DH;
        const __nv_bfloat16* Ql = g_qul + ((size_t)bh * QL + i0) * DH;
#pragma unroll
        for (int rep = 0; rep < 4; ++rep) {
            int ci = t + rep * 256;
            int row = ci >> 3, kc = ci & 7;
            uint32_t dst = sb + AQ_OFF + row * SRS + kc * 16;
            CP16(dst, Qh + (size_t)row * DH + kc * 8);
            CP16(dst + 18432u, Ql + (size_t)row * DH + kc * 8);
        }
    }
    CP_COMMIT();

    auto loadKV = [&](int c) {
        uint32_t kd = sb + AK_OFF + (uint32_t)(c & 1) * ABUF;
        uint32_t vd = sb + AV_OFF + (uint32_t)(c & 1) * ABUF;
#pragma unroll
        for (int rep = 0; rep < 4; ++rep) {
            int ci = t + rep * 256;
            int row = ci >> 3, kc = ci & 7;
            uint32_t o = row * SRS + kc * 16;
            CP16(kd + o, Kh + (size_t)(c * FCH + row) * DH + kc * 8);
            CP16(kd + o + 18432u, Klo + (size_t)(c * FCH + row) * DH + kc * 8);
            CP16(vd + o, Vjh + (size_t)(c * FCH + row) * DH + kc * 8);
            CP16(vd + o + 18432u, Vjl + (size_t)(c * FCH + row) * DH + kc * 8);
        }
    };

    const int nch = (ML + i0 + 128) / FCH;
    loadKV(0); CP_COMMIT();
    loadKV(1); CP_COMMIT();

    const int mrow = lane & 15, khalf = lane >> 4;
    const int brow = lane & 7, bkh = (lane >> 3) & 1, bpair = lane >> 4;
    const int lane16 = lane & 15;
    uint32_t aqh[4][4], aql[4][4];
    CP_WAIT(2);
    __syncthreads();
#pragma unroll
    for (int kf = 0; kf < 4; ++kf) {
        uint32_t aaddr = sb + AQ_OFF + (warp_m + mrow) * SRS + (kf * 16 + khalf * 8) * 2;
        ldmx4(aqh[kf], aaddr);
        ldmx4(aql[kf], aaddr + 18432u);
    }

    const int r0 = lane >> 2;
    const int colb = (lane & 3) * 2;
    const float* bdr0 = g_bd + ((size_t)bh * QL + i0 + warp_m + r0) * KL;
    const float* bdr1 = bdr0 + (size_t)8 * KL;
    const int lim0 = ML + i0 + warp_m + r0;
    const int lim1 = lim0 + 8;

    float pvacc[8][4];
#pragma unroll
    for (int nf = 0; nf < 8; ++nf)
#pragma unroll
        for (int q = 0; q < 4; ++q) pvacc[nf][q] = 0.f;
    float ssum0 = 0.f, ssum1 = 0.f;
    float mold0 = -1e30f, mold1 = -1e30f;

    for (int c = 0; c < nch; ++c) {
        CP_WAIT(1);
        __syncthreads();
        const uint32_t kst = sb + AK_OFF + (uint32_t)(c & 1) * ABUF;
        const uint32_t vst = sb + AV_OFF + (uint32_t)(c & 1) * ABUF;
        const int j0 = c * FCH;

        // ---- S = (q+u) . K^T  (x4 pair loads of K fragments) ----
        float S[16][4];
#pragma unroll
        for (int nf2 = 0; nf2 < 8; ++nf2) {
            S[2 * nf2][0] = S[2 * nf2][1] = S[2 * nf2][2] = S[2 * nf2][3] = 0.f;
            S[2 * nf2 + 1][0] = S[2 * nf2 + 1][1] = S[2 * nf2 + 1][2] = S[2 * nf2 + 1][3] = 0.f;
#pragma unroll
            for (int kf = 0; kf < 4; ++kf) {
                uint32_t baddr = kst + ((nf2 * 2 + bpair) * 8 + brow) * SRS
                               + (kf * 16 + bkh * 8) * 2;
                uint32_t b4h[4], b4l[4];
                ldmx4(b4h, baddr);
                ldmx4(b4l, baddr + 18432u);
                mma16816(S[2 * nf2],     aqh[kf], &b4h[0]);
                mma16816(S[2 * nf2],     aqh[kf], &b4l[0]);
                mma16816(S[2 * nf2],     aql[kf], &b4h[0]);
                mma16816(S[2 * nf2 + 1], aqh[kf], &b4h[2]);
                mma16816(S[2 * nf2 + 1], aqh[kf], &b4l[2]);
                mma16816(S[2 * nf2 + 1], aql[kf], &b4h[2]);
            }
        }

        // ---- + BD, scale, mask, row max ----
        const bool nomask = (j0 + 127) <= lim0;
        float mx0 = -1e30f, mx1 = -1e30f;
#pragma unroll
        for (int nf = 0; nf < 16; ++nf) {
            int jc = j0 + nf * 8 + colb;
            float2 b0 = *(const float2*)(bdr0 + jc);
            float2 b1 = *(const float2*)(bdr1 + jc);
            float s0 = (S[nf][0] + b0.x) * 0.125f;
            float s1 = (S[nf][1] + b0.y) * 0.125f;
            float s2 = (S[nf][2] + b1.x) * 0.125f;
            float s3 = (S[nf][3] + b1.y) * 0.125f;
            if (!nomask) {
                s0 = (jc     <= lim0) ? s0 : -1e30f;
                s1 = (jc + 1 <= lim0) ? s1 : -1e30f;
                s2 = (jc     <= lim1) ? s2 : -1e30f;
                s3 = (jc + 1 <= lim1) ? s3 : -1e30f;
            }
            S[nf][0] = s0; S[nf][1] = s1; S[nf][2] = s2; S[nf][3] = s3;
            mx0 = fmaxf(mx0, fmaxf(s0, s1));
            mx1 = fmaxf(mx1, fmaxf(s2, s3));
        }
        mx0 = fmaxf(mx0, __shfl_xor_sync(0xffffffffu, mx0, 1));
        mx0 = fmaxf(mx0, __shfl_xor_sync(0xffffffffu, mx0, 2));
        mx1 = fmaxf(mx1, __shfl_xor_sync(0xffffffffu, mx1, 1));
        mx1 = fmaxf(mx1, __shfl_xor_sync(0xffffffffu, mx1, 2));
        const float mnew0 = fmaxf(mold0, mx0);
        const float mnew1 = fmaxf(mold1, mx1);
        const float sc0 = __expf(mold0 - mnew0);
        const float sc1 = __expf(mold1 - mnew1);
        mold0 = mnew0; mold1 = mnew1;
        ssum0 *= sc0; ssum1 *= sc1;
#pragma unroll
        for (int nf = 0; nf < 8; ++nf) {
            pvacc[nf][0] *= sc0; pvacc[nf][1] *= sc0;
            pvacc[nf][2] *= sc1; pvacc[nf][3] *= sc1;
        }
#pragma unroll
        for (int nf = 0; nf < 16; ++nf) {
            S[nf][0] = __expf(S[nf][0] - mnew0);
            S[nf][1] = __expf(S[nf][1] - mnew0);
            S[nf][2] = __expf(S[nf][2] - mnew1);
            S[nf][3] = __expf(S[nf][3] - mnew1);
            ssum0 += S[nf][0] + S[nf][1];
            ssum1 += S[nf][2] + S[nf][3];
        }

        // ---- P @ V (x4.trans pair loads of V fragments) ----
#pragma unroll
        for (int kf = 0; kf < 8; ++kf) {
            uint32_t pah[4], pal[4];
            __nv_bfloat16 h0, l0, h1, l1;
            split1(S[2 * kf][0], h0, l0);     split1(S[2 * kf][1], h1, l1);
            pah[0] = pack2(h0, h1);           pal[0] = pack2(l0, l1);
            split1(S[2 * kf][2], h0, l0);     split1(S[2 * kf][3], h1, l1);
            pah[1] = pack2(h0, h1);           pal[1] = pack2(l0, l1);
            split1(S[2 * kf + 1][0], h0, l0); split1(S[2 * kf + 1][1], h1, l1);
            pah[2] = pack2(h0, h1);           pal[2] = pack2(l0, l1);
            split1(S[2 * kf + 1][2], h0, l0); split1(S[2 * kf + 1][3], h1, l1);
            pah[3] = pack2(h0, h1);           pal[3] = pack2(l0, l1);
#pragma unroll
            for (int nf2 = 0; nf2 < 4; ++nf2) {
                uint32_t baddr = vst + (kf * 16 + lane16) * SRS + (nf2 * 2 + bpair) * 16;
                uint32_t b4h[4], b4l[4];
                ldmx4t(b4h, baddr);
                ldmx4t(b4l, baddr + 18432u);
                mma16816(pvacc[2 * nf2],     pah, &b4h[0]);
                mma16816(pvacc[2 * nf2],     pah, &b4l[0]);
                mma16816(pvacc[2 * nf2],     pal, &b4h[0]);
                mma16816(pvacc[2 * nf2 + 1], pah, &b4h[2]);
                mma16816(pvacc[2 * nf2 + 1], pah, &b4l[2]);
                mma16816(pvacc[2 * nf2 + 1], pal, &b4h[2]);
            }
        }

        __syncthreads();
        if (c + 2 < nch) loadKV(c + 2);
        CP_COMMIT();
    }

    // ---- epilogue: normalize, split to bf16 hi/lo, store to g_oh/g_ol ----
    ssum0 += __shfl_xor_sync(0xffffffffu, ssum0, 1);
    ssum0 += __shfl_xor_sync(0xffffffffu, ssum0, 2);
    ssum1 += __shfl_xor_sync(0xffffffffu, ssum1, 1);
    ssum1 += __shfl_xor_sync(0xffffffffu, ssum1, 2);
    const float iv0 = 1.f / ssum0;
    const float iv1 = 1.f / ssum1;
    const size_t orow0 = (size_t)(b * QL + i0 + warp_m + r0) * DM + h * DH;
    const size_t orow1 = orow0 + (size_t)8 * DM;
#pragma unroll
    for (int nf = 0; nf < 8; ++nf) {
        int d = nf * 8 + colb;
        __nv_bfloat16 hh0, ll0, hh1, ll1;
        split1(pvacc[nf][0] * iv0, hh0, ll0);
        split1(pvacc[nf][1] * iv0, hh1, ll1);
        *(uint32_t*)(g_oh + orow0 + d) = pack2(hh0, hh1);
        *(uint32_t*)(g_ol + orow0 + d) = pack2(ll0, ll1);
        split1(pvacc[nf][2] * iv1, hh0, ll0);
        split1(pvacc[nf][3] * iv1, hh1, ll1);
        *(uint32_t*)(g_oh + orow1 + d) = pack2(hh0, hh1);
        *(uint32_t*)(g_ol + orow1 + d) = pack2(ll0, ll1);
    }
}

// =========================== launch =======================================
extern "C" void kernel_launch(void* const* d_in, const int* in_sizes, int n_in,
                              void* d_out, int out_size)
{
    const float* inputs = (const float*)d_in[0];
    const float* mem    = (const float*)d_in[1];
    const float* r      = (const float*)d_in[2];
    const float* W_qkv  = (const float*)d_in[3];
    const float* b_qkv  = (const float*)d_in[4];
    const float* W_r    = (const float*)d_in[5];
    const float* b_r    = (const float*)d_in[6];
    const float* W_o    = (const float*)d_in[7];
    const float* b_o    = (const float*)d_in[8];
    const float* u      = (const float*)d_in[9];
    const float* v      = (const float*)d_in[10];
    float* out = (float*)d_out;

    __nv_bfloat16 *pah, *pal, *prh, *prl, *poh, *pol;
    __nv_bfloat16 *pwqh, *pwql, *pwrh, *pwrl, *pwoh, *pwol;
    cudaGetSymbolAddress((void**)&pah,   g_ah);
    cudaGetSymbolAddress((void**)&pal,   g_al);
    cudaGetSymbolAddress((void**)&prh,   g_rh);
    cudaGetSymbolAddress((void**)&prl,   g_rl);
    cudaGetSymbolAddress((void**)&poh,   g_oh);
    cudaGetSymbolAddress((void**)&pol,   g_ol);
    cudaGetSymbolAddress((void**)&pwqh,  g_wqh);
    cudaGetSymbolAddress((void**)&pwql,  g_wql);
    cudaGetSymbolAddress((void**)&pwrh,  g_wrh);
    cudaGetSymbolAddress((void**)&pwrl,  g_wrl);
    cudaGetSymbolAddress((void**)&pwoh,  g_woh);
    cudaGetSymbolAddress((void**)&pwol,  g_wol);

    cudaFuncSetAttribute(gemm_bf3<0>, cudaFuncAttributeMaxDynamicSharedMemorySize, GEMM_SMEM);
    cudaFuncSetAttribute(gemm_bf3<1>, cudaFuncAttributeMaxDynamicSharedMemorySize, GEMM_SMEM);
    cudaFuncSetAttribute(gemm_bf3<2>, cudaFuncAttributeMaxDynamicSharedMemorySize, GEMM_SMEM);
    cudaFuncSetAttribute(bd_mma, cudaFuncAttributeMaxDynamicSharedMemorySize, SCORE_SMEM);
    cudaFuncSetAttribute(attn_flash, cudaFuncAttributeMaxDynamicSharedMemorySize, ATTN_SMEM);

    dim3 blk(256);

    // --- A-side / weight splits ---
    split_concat<<<4096, blk>>>(mem, inputs, pah, pal);
    split_plain<<<4096, blk>>>(r, prh, prl);
    split_transpose<<<dim3(3072 / 32, 1024 / 32), blk>>>(W_qkv, pwqh, pwql, 3072);
    split_transpose<<<dim3(1024 / 32, 1024 / 32), blk>>>(W_r,   pwrh, pwrl, 1024);
    split_transpose<<<dim3(1024 / 32, 1024 / 32), blk>>>(W_o,   pwoh, pwol, 1024);

    // 1) qkv projection with fused per-head operand epilogue
    gemm_bf3<1><<<dim3(3072 / 128, 4096 / 128), blk, GEMM_SMEM>>>(
        pah, pal, pwqh, pwql, b_qkv, nullptr, 3072, u, v);
    // 2) r projection with fused rr epilogue
    gemm_bf3<2><<<dim3(1024 / 128, 4096 / 128), blk, GEMM_SMEM>>>(
        prh, prl, pwrh, pwrl, b_r, nullptr, 1024, nullptr, nullptr);

    // 3) BD (pre-shifted, fp32) -> g_bd
    bd_mma<<<dim3(KL / 128, QL / 128, BQ * NH), blk, SCORE_SMEM>>>();

    // 4) fused AC + online softmax + P@V -> g_oh/g_ol
    attn_flash<<<dim3(QL / 128, BQ * NH), blk, ATTN_SMEM>>>();

    // 5) final projection -> d_out
    gemm_bf3<0><<<dim3(1024 / 128, 2048 / 128), blk, GEMM_SMEM>>>(
        poh, pol, pwoh, pwol, b_o, out, 1024, nullptr, nullptr);
}

// round 14
// speedup vs baseline: 1.1187x; 1.0592x over previous
#include <cuda_runtime.h>
#include <cuda_bf16.h>
#include <cstdint>
#include <cstddef>

#define BQ 2
#define QL 1024
#define ML 1024
#define KL 2048
#define DM 1024
#define NH 16
#define DH 64

// ---------------- scratch (device globals: allocation-free) ----------------
__device__ float g_bd[(size_t)32 * 1024 * 2048];    // BD (pre-shifted) [B*H, Q, K]

__device__ __nv_bfloat16 g_ah[(size_t)4096 * 1024], g_al[(size_t)4096 * 1024];
__device__ __nv_bfloat16 g_rh[(size_t)4096 * 1024], g_rl[(size_t)4096 * 1024];
__device__ __nv_bfloat16 g_oh[(size_t)2048 * 1024], g_ol[(size_t)2048 * 1024];
__device__ __nv_bfloat16 g_wqh[(size_t)3072 * 1024], g_wql[(size_t)3072 * 1024];
__device__ __nv_bfloat16 g_wrh[(size_t)1024 * 1024], g_wrl[(size_t)1024 * 1024];
__device__ __nv_bfloat16 g_woh[(size_t)1024 * 1024], g_wol[(size_t)1024 * 1024];

__device__ __nv_bfloat16 g_quh[(size_t)32 * 1024 * 64], g_qul[(size_t)32 * 1024 * 64];
__device__ __nv_bfloat16 g_qvh[(size_t)32 * 1024 * 64], g_qvl[(size_t)32 * 1024 * 64];
__device__ __nv_bfloat16 g_khh[(size_t)32 * 2048 * 64], g_khl[(size_t)32 * 2048 * 64];
__device__ __nv_bfloat16 g_rrh[(size_t)32 * 2048 * 64], g_rrl[(size_t)32 * 2048 * 64];
__device__ __nv_bfloat16 g_vjh[(size_t)32 * 2048 * 64], g_vjl[(size_t)32 * 2048 * 64];

// ======================= helpers ===========================================
__device__ __forceinline__ uint32_t smem_u32(const void* p) {
    uint32_t a;
    asm("{ .reg .u64 t; cvta.to.shared.u64 t, %1; cvt.u32.u64 %0, t; }"
        : "=r"(a) : "l"(p));
    return a;
}
__device__ __forceinline__ void split1(float x, __nv_bfloat16& h, __nv_bfloat16& l) {
    h = __float2bfloat16_rn(x);
    l = __float2bfloat16_rn(x - __bfloat162float(h));
}
__device__ __forceinline__ uint32_t pack2(__nv_bfloat16 a, __nv_bfloat16 b) {
    __nv_bfloat162 v = make_bfloat162(a, b);
    return *(uint32_t*)&v;
}
__device__ __forceinline__ void ldmx4(uint32_t a[4], uint32_t addr) {
    asm volatile("ldmatrix.sync.aligned.m8n8.x4.shared.b16 {%0,%1,%2,%3}, [%4];"
        : "=r"(a[0]), "=r"(a[1]), "=r"(a[2]), "=r"(a[3]) : "r"(addr));
}
__device__ __forceinline__ void ldmx4t(uint32_t a[4], uint32_t addr) {
    asm volatile("ldmatrix.sync.aligned.m8n8.x4.trans.shared.b16 {%0,%1,%2,%3}, [%4];"
        : "=r"(a[0]), "=r"(a[1]), "=r"(a[2]), "=r"(a[3]) : "r"(addr));
}
__device__ __forceinline__ void mma16816(float c[4], const uint32_t a[4], const uint32_t b[2]) {
    asm volatile("mma.sync.aligned.m16n8k16.row.col.f32.bf16.bf16.f32 "
        "{%0,%1,%2,%3}, {%4,%5,%6,%7}, {%8,%9}, {%0,%1,%2,%3};"
        : "+f"(c[0]), "+f"(c[1]), "+f"(c[2]), "+f"(c[3])
        : "r"(a[0]), "r"(a[1]), "r"(a[2]), "r"(a[3]), "r"(b[0]), "r"(b[1]));
}
#define CP16(dst, src) \
    asm volatile("cp.async.cg.shared.global [%0], [%1], 16;" :: "r"(dst), "l"(src) : "memory")
#define CP_COMMIT() asm volatile("cp.async.commit_group;" ::: "memory")
#define CP_WAIT(n)  asm volatile("cp.async.wait_group %0;" :: "n"(n) : "memory")

// ===================== prep: fused split kernel =============================
// blocks [0, 4096): concat(mem, inputs) -> g_ah/g_al
// blocks [4096, 8192): r -> g_rh/g_rl
__global__ __launch_bounds__(256)
void fused_split(const float* __restrict__ mem, const float* __restrict__ inp,
                 const float* __restrict__ r)
{
    const bool isr = blockIdx.x >= 4096;
    size_t idx = ((size_t)(blockIdx.x & 4095) * 256 + threadIdx.x) * 4;
    const float* src;
    __nv_bfloat16 *hi, *lo;
    if (!isr) {
        size_t row = idx >> 10;
        int col = (int)(idx & 1023);
        int b = (int)(row >> 11);
        int k = (int)(row & 2047);
        src = ((k < ML) ? mem + ((size_t)(b * ML + k) << 10)
                        : inp + ((size_t)(b * QL + (k - ML)) << 10)) + col;
        hi = g_ah + idx; lo = g_al + idx;
    } else {
        src = r + idx;
        hi = g_rh + idx; lo = g_rl + idx;
    }
    float4 v = *(const float4*)src;
    __nv_bfloat16 h0, h1, h2, h3, l0, l1, l2, l3;
    split1(v.x, h0, l0); split1(v.y, h1, l1);
    split1(v.z, h2, l2); split1(v.w, h3, l3);
    __nv_bfloat162* H = (__nv_bfloat162*)hi;
    __nv_bfloat162* L = (__nv_bfloat162*)lo;
    H[0] = make_bfloat162(h0, h1); H[1] = make_bfloat162(h2, h3);
    L[0] = make_bfloat162(l0, l1); L[1] = make_bfloat162(l2, l3);
}

// ===================== prep: fused transpose kernel ==========================
// x in [0,96): W_qkv ; [96,128): W_r ; [128,160): W_o
__global__ __launch_bounds__(256)
void fused_transpose(const float* __restrict__ Wq, const float* __restrict__ Wr,
                     const float* __restrict__ Wo)
{
    __shared__ float s[32][33];
    int bx = blockIdx.x;
    const float* in;
    __nv_bfloat16 *hi, *lo;
    int N;
    if (bx < 96) {
        in = Wq; hi = g_wqh; lo = g_wql; N = 3072;
    } else if (bx < 128) {
        in = Wr; hi = g_wrh; lo = g_wrl; N = 1024; bx -= 96;
    } else {
        in = Wo; hi = g_woh; lo = g_wol; N = 1024; bx -= 128;
    }
    const int nx = bx * 32;
    const int ky = blockIdx.y * 32;
    const int tx = threadIdx.x & 31;
    const int ty = threadIdx.x >> 5;
#pragma unroll
    for (int rr = 0; rr < 32; rr += 8)
        s[ty + rr][tx] = in[(size_t)(ky + ty + rr) * N + nx + tx];
    __syncthreads();
#pragma unroll
    for (int rr = 0; rr < 32; rr += 8) {
        float x = s[tx][ty + rr];
        __nv_bfloat16 h, l;
        split1(x, h, l);
        size_t o = (size_t)(nx + ty + rr) * DM + ky + tx;
        hi[o] = h;
        lo[o] = l;
    }
}

// ============== dense GEMM: mma.sync bf16 3-term split ======================
#define RS 80
#define ARRB (128 * RS)
#define STGB (4 * ARRB)
#define NSTG 4
#define GEMM_SMEM (NSTG * STGB)

__device__ __forceinline__ void store_opnd_rt(int mode, int m, int n, float x0, float x1,
                                              const float* __restrict__ u,
                                              const float* __restrict__ v)
{
    int b = m >> 11, tok = m & 2047;
    __nv_bfloat16 h0, l0, h1, l1;
    if (mode == 2) {
        int h = n >> 6, d = n & 63;
        size_t o = ((size_t)(b * NH + h) * KL + tok) * DH + d;
        split1(x0, h0, l0); split1(x1, h1, l1);
        *(uint32_t*)(g_rrh + o) = pack2(h0, h1);
        *(uint32_t*)(g_rrl + o) = pack2(l0, l1);
    } else if (n < 1024) {
        int h = n >> 6, d = n & 63, i = tok - ML;
        size_t o = ((size_t)(b * NH + h) * QL + i) * DH + d;
        split1(x0 + u[n], h0, l0); split1(x1 + u[n + 1], h1, l1);
        *(uint32_t*)(g_quh + o) = pack2(h0, h1);
        *(uint32_t*)(g_qul + o) = pack2(l0, l1);
        split1(x0 + v[n], h0, l0); split1(x1 + v[n + 1], h1, l1);
        *(uint32_t*)(g_qvh + o) = pack2(h0, h1);
        *(uint32_t*)(g_qvl + o) = pack2(l0, l1);
    } else if (n < 2048) {
        int h = (n - 1024) >> 6, d = n & 63;
        size_t o = ((size_t)(b * NH + h) * KL + tok) * DH + d;
        split1(x0, h0, l0); split1(x1, h1, l1);
        *(uint32_t*)(g_vjh + o) = pack2(h0, h1);
        *(uint32_t*)(g_vjl + o) = pack2(l0, l1);
    } else {
        int h = (n - 2048) >> 6, d = n & 63;
        size_t o = ((size_t)(b * NH + h) * KL + tok) * DH + d;
        split1(x0, h0, l0); split1(x1, h1, l1);
        *(uint32_t*)(g_khh + o) = pack2(h0, h1);
        *(uint32_t*)(g_khl + o) = pack2(l0, l1);
    }
}

// GEMM core shared by all modes. mode: 0 = fp32 C, 1 = qkv epi, 2 = rr epi.
__device__ __forceinline__
void gemm_core(int mode, int m0, int n0,
               const __nv_bfloat16* __restrict__ Ah, const __nv_bfloat16* __restrict__ Al,
               const __nv_bfloat16* __restrict__ Bh, const __nv_bfloat16* __restrict__ Bl,
               const float* __restrict__ bias, float* __restrict__ C, int N,
               const float* __restrict__ u, const float* __restrict__ v, char* sm)
{
    const uint32_t sb = smem_u32(sm);
    const int t = threadIdx.x;
    const int lane = t & 31;
    const int wid = t >> 5;
    const int warp_m = (wid & 1) * 64;
    const int warp_n = (wid >> 1) * 32;

    const __nv_bfloat16* srcs[4] = {
        Ah + (size_t)m0 * DM, Al + (size_t)m0 * DM,
        Bh + (size_t)n0 * DM, Bl + (size_t)n0 * DM
    };

    auto issue_stage = [&](int c) {
        uint32_t dst0 = sb + (uint32_t)(c & 3) * STGB;
#pragma unroll
        for (int arr = 0; arr < 4; ++arr) {
#pragma unroll
            for (int rep = 0; rep < 2; ++rep) {
                int ci = t + rep * 256;
                int row = ci >> 2;
                int kc = ci & 3;
                uint32_t dst = dst0 + arr * ARRB + row * RS + kc * 16;
                const __nv_bfloat16* src = srcs[arr] + (size_t)row * DM + c * 32 + kc * 8;
                CP16(dst, src);
            }
        }
    };

    float acc[4][4][4];
#pragma unroll
    for (int im = 0; im < 4; ++im)
#pragma unroll
        for (int jn = 0; jn < 4; ++jn)
#pragma unroll
            for (int q = 0; q < 4; ++q) acc[im][jn][q] = 0.f;

#pragma unroll
    for (int s = 0; s < NSTG - 1; ++s) { issue_stage(s); CP_COMMIT(); }

    const int mrow = lane & 15;
    const int khalf = lane >> 4;
    const int brow = lane & 7;
    const int bkh = (lane >> 3) & 1;
    const int bpair = lane >> 4;

    const int NCH = DM / 32;
    for (int c = 0; c < NCH; ++c) {
        CP_WAIT(2);
        __syncthreads();
        if (c + 3 < NCH) issue_stage(c + 3);
        CP_COMMIT();

        const uint32_t st = sb + (uint32_t)(c & 3) * STGB;
#pragma unroll
        for (int kk = 0; kk < 32; kk += 16) {
            uint32_t ah[4][4], al[4][4];
#pragma unroll
            for (int im = 0; im < 4; ++im) {
                uint32_t aaddr = st + (warp_m + im * 16 + mrow) * RS + (kk + khalf * 8) * 2;
                ldmx4(ah[im], aaddr);
                ldmx4(al[im], aaddr + ARRB);
            }
#pragma unroll
            for (int j2 = 0; j2 < 2; ++j2) {
                uint32_t baddr = st + 2 * ARRB
                    + (warp_n + (j2 * 2 + bpair) * 8 + brow) * RS + (kk + bkh * 8) * 2;
                uint32_t b4h[4], b4l[4];
                ldmx4(b4h, baddr);
                ldmx4(b4l, baddr + ARRB);
#pragma unroll
                for (int im = 0; im < 4; ++im) {
                    mma16816(acc[im][2 * j2],     ah[im], &b4h[0]);
                    mma16816(acc[im][2 * j2],     ah[im], &b4l[0]);
                    mma16816(acc[im][2 * j2],     al[im], &b4h[0]);
                    mma16816(acc[im][2 * j2 + 1], ah[im], &b4h[2]);
                    mma16816(acc[im][2 * j2 + 1], ah[im], &b4l[2]);
                    mma16816(acc[im][2 * j2 + 1], al[im], &b4h[2]);
                }
            }
        }
    }

    if (mode == 0) {
#pragma unroll
        for (int im = 0; im < 4; ++im) {
            int m = m0 + warp_m + im * 16 + (lane >> 2);
#pragma unroll
            for (int jn = 0; jn < 4; ++jn) {
                int n = n0 + warp_n + jn * 8 + (lane & 3) * 2;
                float b0 = bias[n], b1 = bias[n + 1];
                float2 v0, v1;
                v0.x = acc[im][jn][0] + b0; v0.y = acc[im][jn][1] + b1;
                v1.x = acc[im][jn][2] + b0; v1.y = acc[im][jn][3] + b1;
                *(float2*)(C + (size_t)m * N + n) = v0;
                *(float2*)(C + (size_t)(m + 8) * N + n) = v1;
            }
        }
    } else {
#pragma unroll
        for (int im = 0; im < 4; ++im) {
            int m = m0 + warp_m + im * 16 + (lane >> 2);
#pragma unroll
            for (int jn = 0; jn < 4; ++jn) {
                int n = n0 + warp_n + jn * 8 + (lane & 3) * 2;
                float b0 = bias[n], b1 = bias[n + 1];
                store_opnd_rt(mode, m, n, acc[im][jn][0] + b0, acc[im][jn][1] + b1, u, v);
                store_opnd_rt(mode, m + 8, n, acc[im][jn][2] + b0, acc[im][jn][3] + b1, u, v);
            }
        }
    }
}

// fused qkv + r projection: blockIdx.x < 24 -> qkv column, else -> r column
__global__ __launch_bounds__(256, 1)
void gemm_fused12(const float* __restrict__ b_qkv, const float* __restrict__ b_r,
                  const float* __restrict__ u, const float* __restrict__ v)
{
    extern __shared__ char sm[];
    const int m0 = blockIdx.y * 128;
    if (blockIdx.x < 24) {
        const int n0 = blockIdx.x * 128;
        if (n0 < 1024 && ((m0 & 2047) + 128) <= ML) return;   // skip q cols for mem rows
        gemm_core(1, m0, n0, g_ah, g_al, g_wqh, g_wql, b_qkv, nullptr, 3072, u, v, sm);
    } else {
        const int n0 = (blockIdx.x - 24) * 128;
        gemm_core(2, m0, n0, g_rh, g_rl, g_wrh, g_wrl, b_r, nullptr, 1024, nullptr, nullptr, sm);
    }
}

// final projection (fp32 out)
__global__ __launch_bounds__(256, 1)
void gemm_out(const float* __restrict__ bias, float* __restrict__ C)
{
    extern __shared__ char sm[];
    gemm_core(0, blockIdx.y * 128, blockIdx.x * 128,
              g_oh, g_ol, g_woh, g_wol, bias, C, 1024, nullptr, nullptr, sm);
}

// ============== BD score GEMM (mma, K=64, x4 pair B loads, occ 2) ===========
#define SRS 144
#define SARRB (128 * SRS)
#define SCORE_SMEM (4 * SARRB)

__global__ __launch_bounds__(256, 2)
void bd_mma()
{
    const int bh = blockIdx.z;
    const int i0 = blockIdx.y * 128;
    const int p0 = blockIdx.x * 128;
    if (i0 + p0 + 254 < QL - 1) return;

    extern __shared__ char sm[];
    const uint32_t sb = smem_u32(sm);
    const int t = threadIdx.x;
    const int lane = t & 31;
    const int wid = t >> 5;
    const int warp_m = (wid & 1) * 64;
    const int warp_n = (wid >> 1) * 32;

    const __nv_bfloat16* srcs[4] = {
        g_qvh + ((size_t)bh * QL + i0) * DH,
        g_qvl + ((size_t)bh * QL + i0) * DH,
        g_rrh + ((size_t)bh * KL + p0) * DH,
        g_rrl + ((size_t)bh * KL + p0) * DH
    };
#pragma unroll
    for (int arr = 0; arr < 4; ++arr) {
#pragma unroll
        for (int rep = 0; rep < 4; ++rep) {
            int ci = t + rep * 256;
            int row = ci >> 3;
            int kc = ci & 7;
            uint32_t dst = sb + arr * SARRB + row * SRS + kc * 16;
            CP16(dst, srcs[arr] + (size_t)row * DH + kc * 8);
        }
    }
    CP_COMMIT();
    CP_WAIT(0);
    __syncthreads();

    float acc[4][4][4];
#pragma unroll
    for (int im = 0; im < 4; ++im)
#pragma unroll
        for (int jn = 0; jn < 4; ++jn)
#pragma unroll
            for (int q = 0; q < 4; ++q) acc[im][jn][q] = 0.f;

    const int mrow = lane & 15;
    const int khalf = lane >> 4;
    const int brow = lane & 7;
    const int bkh = (lane >> 3) & 1;
    const int bpair = lane >> 4;
#pragma unroll
    for (int kk = 0; kk < 64; kk += 16) {
        uint32_t ah[4][4], al[4][4];
#pragma unroll
        for (int im = 0; im < 4; ++im) {
            uint32_t aaddr = sb + (warp_m + im * 16 + mrow) * SRS + (kk + khalf * 8) * 2;
            ldmx4(ah[im], aaddr);
            ldmx4(al[im], aaddr + SARRB);
        }
#pragma unroll
        for (int j2 = 0; j2 < 2; ++j2) {
            uint32_t baddr = sb + 2 * SARRB
                + (warp_n + (j2 * 2 + bpair) * 8 + brow) * SRS + (kk + bkh * 8) * 2;
            uint32_t b4h[4], b4l[4];
            ldmx4(b4h, baddr);
            ldmx4(b4l, baddr + SARRB);
#pragma unroll
            for (int im = 0; im < 4; ++im) {
                mma16816(acc[im][2 * j2],     ah[im], &b4h[0]);
                mma16816(acc[im][2 * j2],     ah[im], &b4l[0]);
                mma16816(acc[im][2 * j2],     al[im], &b4h[0]);
                mma16816(acc[im][2 * j2 + 1], ah[im], &b4h[2]);
                mma16816(acc[im][2 * j2 + 1], ah[im], &b4l[2]);
                mma16816(acc[im][2 * j2 + 1], al[im], &b4h[2]);
            }
        }
    }

#pragma unroll
    for (int im = 0; im < 4; ++im) {
        int m = i0 + warp_m + im * 16 + (lane >> 2);
        float* r0 = g_bd + ((size_t)bh * QL + m) * KL;
        float* r1 = g_bd + ((size_t)bh * QL + m + 8) * KL;
        int sh0 = m - (QL - 1);
        int sh1 = m + 8 - (QL - 1);
#pragma unroll
        for (int jn = 0; jn < 4; ++jn) {
            int p = p0 + warp_n + jn * 8 + (lane & 3) * 2;
            int j0a = p + sh0;
            int j1a = p + sh1;
            if (j0a >= 0)     r0[j0a]     = acc[im][jn][0];
            if (j0a + 1 >= 0) r0[j0a + 1] = acc[im][jn][1];
            if (j1a >= 0)     r1[j1a]     = acc[im][jn][2];
            if (j1a + 1 >= 0) r1[j1a + 1] = acc[im][jn][3];
        }
    }
}

// ========== warp-autonomous flash attention (x4 pair loads) ================
#define FCH 128
#define AQ_OFF 0u
#define AK_OFF 36864u
#define AV_OFF 110592u
#define ABUF 36864u
#define ATTN_SMEM 184320

__global__ __launch_bounds__(256, 1)
void attn_flash()
{
    extern __shared__ char sm[];
    const uint32_t sb = smem_u32(sm);
    const int bh = blockIdx.y;
    const int b = bh >> 4, h = bh & 15;
    const int i0 = (gridDim.x - 1 - blockIdx.x) * 128;
    const int t = threadIdx.x, lane = t & 31, wid = t >> 5;
    const int warp_m = wid * 16;

    const __nv_bfloat16* Kh  = g_khh + (size_t)bh * KL * DH;
    const __nv_bfloat16* Klo = g_khl + (size_t)bh * KL * DH;
    const __nv_bfloat16* Vjh = g_vjh + (size_t)bh * KL * DH;
    const __nv_bfloat16* Vjl = g_vjl + (size_t)bh * KL * DH;

    {
        const __nv_bfloat16* Qh = g_quh + ((size_t)bh * QL + i0) * DH;
        const __nv_bfloat16* Ql = g_qul + ((size_t)bh * QL + i0) * DH;
#pragma unroll
        for (int rep = 0; rep < 4; ++rep) {
            int ci = t + rep * 256;
            int row = ci >> 3, kc = ci & 7;
            uint32_t dst = sb + AQ_OFF + row * SRS + kc * 16;
            CP16(dst, Qh + (size_t)row * DH + kc * 8);
            CP16(dst + 18432u, Ql + (size_t)row * DH + kc * 8);
        }
    }
    CP_COMMIT();

    auto loadKV = [&](int c) {
        uint32_t kd = sb + AK_OFF + (uint32_t)(c & 1) * ABUF;
        uint32_t vd = sb + AV_OFF + (uint32_t)(c & 1) * ABUF;
#pragma unroll
        for (int rep = 0; rep < 4; ++rep) {
            int ci = t + rep * 256;
            int row = ci >> 3, kc = ci & 7;
            uint32_t o = row * SRS + kc * 16;
            CP16(kd + o, Kh + (size_t)(c * FCH + row) * DH + kc * 8);
            CP16(kd + o + 18432u, Klo + (size_t)(c * FCH + row) * DH + kc * 8);
            CP16(vd + o, Vjh + (size_t)(c * FCH + row) * DH + kc * 8);
            CP16(vd + o + 18432u, Vjl + (size_t)(c * FCH + row) * DH + kc * 8);
        }
    };

    const int nch = (ML + i0 + 128) / FCH;
    loadKV(0); CP_COMMIT();
    loadKV(1); CP_COMMIT();

    const int mrow = lane & 15, khalf = lane >> 4;
    const int brow = lane & 7, bkh = (lane >> 3) & 1, bpair = lane >> 4;
    const int lane16 = lane & 15;
    uint32_t aqh[4][4], aql[4][4];
    CP_WAIT(2);
    __syncthreads();
#pragma unroll
    for (int kf = 0; kf < 4; ++kf) {
        uint32_t aaddr = sb + AQ_OFF + (warp_m + mrow) * SRS + (kf * 16 + khalf * 8) * 2;
        ldmx4(aqh[kf], aaddr);
        ldmx4(aql[kf], aaddr + 18432u);
    }

    const int r0 = lane >> 2;
    const int colb = (lane & 3) * 2;
    const float* bdr0 = g_bd + ((size_t)bh * QL + i0 + warp_m + r0) * KL;
    const float* bdr1 = bdr0 + (size_t)8 * KL;
    const int lim0 = ML + i0 + warp_m + r0;
    const int lim1 = lim0 + 8;

    float pvacc[8][4];
#pragma unroll
    for (int nf = 0; nf < 8; ++nf)
#pragma unroll
        for (int q = 0; q < 4; ++q) pvacc[nf][q] = 0.f;
    float ssum0 = 0.f, ssum1 = 0.f;
    float mold0 = -1e30f, mold1 = -1e30f;

    for (int c = 0; c < nch; ++c) {
        CP_WAIT(1);
        __syncthreads();
        const uint32_t kst = sb + AK_OFF + (uint32_t)(c & 1) * ABUF;
        const uint32_t vst = sb + AV_OFF + (uint32_t)(c & 1) * ABUF;
        const int j0 = c * FCH;

        float S[16][4];
#pragma unroll
        for (int nf2 = 0; nf2 < 8; ++nf2) {
            S[2 * nf2][0] = S[2 * nf2][1] = S[2 * nf2][2] = S[2 * nf2][3] = 0.f;
            S[2 * nf2 + 1][0] = S[2 * nf2 + 1][1] = S[2 * nf2 + 1][2] = S[2 * nf2 + 1][3] = 0.f;
#pragma unroll
            for (int kf = 0; kf < 4; ++kf) {
                uint32_t baddr = kst + ((nf2 * 2 + bpair) * 8 + brow) * SRS
                               + (kf * 16 + bkh * 8) * 2;
                uint32_t b4h[4], b4l[4];
                ldmx4(b4h, baddr);
                ldmx4(b4l, baddr + 18432u);
                mma16816(S[2 * nf2],     aqh[kf], &b4h[0]);
                mma16816(S[2 * nf2],     aqh[kf], &b4l[0]);
                mma16816(S[2 * nf2],     aql[kf], &b4h[0]);
                mma16816(S[2 * nf2 + 1], aqh[kf], &b4h[2]);
                mma16816(S[2 * nf2 + 1], aqh[kf], &b4l[2]);
                mma16816(S[2 * nf2 + 1], aql[kf], &b4h[2]);
            }
        }

        const bool nomask = (j0 + 127) <= lim0;
        float mx0 = -1e30f, mx1 = -1e30f;
#pragma unroll
        for (int nf = 0; nf < 16; ++nf) {
            int jc = j0 + nf * 8 + colb;
            float2 b0 = *(const float2*)(bdr0 + jc);
            float2 b1 = *(const float2*)(bdr1 + jc);
            float s0 = (S[nf][0] + b0.x) * 0.125f;
            float s1 = (S[nf][1] + b0.y) * 0.125f;
            float s2 = (S[nf][2] + b1.x) * 0.125f;
            float s3 = (S[nf][3] + b1.y) * 0.125f;
            if (!nomask) {
                s0 = (jc     <= lim0) ? s0 : -1e30f;
                s1 = (jc + 1 <= lim0) ? s1 : -1e30f;
                s2 = (jc     <= lim1) ? s2 : -1e30f;
                s3 = (jc + 1 <= lim1) ? s3 : -1e30f;
            }
            S[nf][0] = s0; S[nf][1] = s1; S[nf][2] = s2; S[nf][3] = s3;
            mx0 = fmaxf(mx0, fmaxf(s0, s1));
            mx1 = fmaxf(mx1, fmaxf(s2, s3));
        }
        mx0 = fmaxf(mx0, __shfl_xor_sync(0xffffffffu, mx0, 1));
        mx0 = fmaxf(mx0, __shfl_xor_sync(0xffffffffu, mx0, 2));
        mx1 = fmaxf(mx1, __shfl_xor_sync(0xffffffffu, mx1, 1));
        mx1 = fmaxf(mx1, __shfl_xor_sync(0xffffffffu, mx1, 2));
        const float mnew0 = fmaxf(mold0, mx0);
        const float mnew1 = fmaxf(mold1, mx1);
        const float sc0 = __expf(mold0 - mnew0);
        const float sc1 = __expf(mold1 - mnew1);
        mold0 = mnew0; mold1 = mnew1;
        ssum0 *= sc0; ssum1 *= sc1;
#pragma unroll
        for (int nf = 0; nf < 8; ++nf) {
            pvacc[nf][0] *= sc0; pvacc[nf][1] *= sc0;
            pvacc[nf][2] *= sc1; pvacc[nf][3] *= sc1;
        }
#pragma unroll
        for (int nf = 0; nf < 16; ++nf) {
            S[nf][0] = __expf(S[nf][0] - mnew0);
            S[nf][1] = __expf(S[nf][1] - mnew0);
            S[nf][2] = __expf(S[nf][2] - mnew1);
            S[nf][3] = __expf(S[nf][3] - mnew1);
            ssum0 += S[nf][0] + S[nf][1];
            ssum1 += S[nf][2] + S[nf][3];
        }

#pragma unroll
        for (int kf = 0; kf < 8; ++kf) {
            uint32_t pah[4], pal[4];
            __nv_bfloat16 h0, l0, h1, l1;
            split1(S[2 * kf][0], h0, l0);     split1(S[2 * kf][1], h1, l1);
            pah[0] = pack2(h0, h1);           pal[0] = pack2(l0, l1);
            split1(S[2 * kf][2], h0, l0);     split1(S[2 * kf][3], h1, l1);
            pah[1] = pack2(h0, h1);           pal[1] = pack2(l0, l1);
            split1(S[2 * kf + 1][0], h0, l0); split1(S[2 * kf + 1][1], h1, l1);
            pah[2] = pack2(h0, h1);           pal[2] = pack2(l0, l1);
            split1(S[2 * kf + 1][2], h0, l0); split1(S[2 * kf + 1][3], h1, l1);
            pah[3] = pack2(h0, h1);           pal[3] = pack2(l0, l1);
#pragma unroll
            for (int nf2 = 0; nf2 < 4; ++nf2) {
                uint32_t baddr = vst + (kf * 16 + lane16) * SRS + (nf2 * 2 + bpair) * 16;
                uint32_t b4h[4], b4l[4];
                ldmx4t(b4h, baddr);
                ldmx4t(b4l, baddr + 18432u);
                mma16816(pvacc[2 * nf2],     pah, &b4h[0]);
                mma16816(pvacc[2 * nf2],     pah, &b4l[0]);
                mma16816(pvacc[2 * nf2],     pal, &b4h[0]);
                mma16816(pvacc[2 * nf2 + 1], pah, &b4h[2]);
                mma16816(pvacc[2 * nf2 + 1], pah, &b4l[2]);
                mma16816(pvacc[2 * nf2 + 1], pal, &b4h[2]);
            }
        }

        __syncthreads();
        if (c + 2 < nch) loadKV(c + 2);
        CP_COMMIT();
    }

    ssum0 += __shfl_xor_sync(0xffffffffu, ssum0, 1);
    ssum0 += __shfl_xor_sync(0xffffffffu, ssum0, 2);
    ssum1 += __shfl_xor_sync(0xffffffffu, ssum1, 1);
    ssum1 += __shfl_xor_sync(0xffffffffu, ssum1, 2);
    const float iv0 = 1.f / ssum0;
    const float iv1 = 1.f / ssum1;
    const size_t orow0 = (size_t)(b * QL + i0 + warp_m + r0) * DM + h * DH;
    const size_t orow1 = orow0 + (size_t)8 * DM;
#pragma unroll
    for (int nf = 0; nf < 8; ++nf) {
        int d = nf * 8 + colb;
        __nv_bfloat16 hh0, ll0, hh1, ll1;
        split1(pvacc[nf][0] * iv0, hh0, ll0);
        split1(pvacc[nf][1] * iv0, hh1, ll1);
        *(uint32_t*)(g_oh + orow0 + d) = pack2(hh0, hh1);
        *(uint32_t*)(g_ol + orow0 + d) = pack2(ll0, ll1);
        split1(pvacc[nf][2] * iv1, hh0, ll0);
        split1(pvacc[nf][3] * iv1, hh1, ll1);
        *(uint32_t*)(g_oh + orow1 + d) = pack2(hh0, hh1);
        *(uint32_t*)(g_ol + orow1 + d) = pack2(ll0, ll1);
    }
}

// =========================== launch =======================================
extern "C" void kernel_launch(void* const* d_in, const int* in_sizes, int n_in,
                              void* d_out, int out_size)
{
    const float* inputs = (const float*)d_in[0];
    const float* mem    = (const float*)d_in[1];
    const float* r      = (const float*)d_in[2];
    const float* W_qkv  = (const float*)d_in[3];
    const float* b_qkv  = (const float*)d_in[4];
    const float* W_r    = (const float*)d_in[5];
    const float* b_r    = (const float*)d_in[6];
    const float* W_o    = (const float*)d_in[7];
    const float* b_o    = (const float*)d_in[8];
    const float* u      = (const float*)d_in[9];
    const float* v      = (const float*)d_in[10];
    float* out = (float*)d_out;

    cudaFuncSetAttribute(gemm_fused12, cudaFuncAttributeMaxDynamicSharedMemorySize, GEMM_SMEM);
    cudaFuncSetAttribute(gemm_out, cudaFuncAttributeMaxDynamicSharedMemorySize, GEMM_SMEM);
    cudaFuncSetAttribute(bd_mma, cudaFuncAttributeMaxDynamicSharedMemorySize, SCORE_SMEM);
    cudaFuncSetAttribute(attn_flash, cudaFuncAttributeMaxDynamicSharedMemorySize, ATTN_SMEM);

    dim3 blk(256);

    // 1) fused A-side splits (concat + r)
    fused_split<<<8192, blk>>>(mem, inputs, r);
    // 2) fused weight transposes (W_qkv | W_r | W_o)
    fused_transpose<<<dim3(160, 32), blk>>>(W_qkv, W_r, W_o);

    // 3) fused qkv + r projections (tail-filling single launch)
    gemm_fused12<<<dim3(32, 32), blk, GEMM_SMEM>>>(b_qkv, b_r, u, v);

    // 4) BD (pre-shifted, fp32) -> g_bd
    bd_mma<<<dim3(KL / 128, QL / 128, BQ * NH), blk, SCORE_SMEM>>>();

    // 5) fused AC + online softmax + P@V -> g_oh/g_ol
    attn_flash<<<dim3(QL / 128, BQ * NH), blk, ATTN_SMEM>>>();

    // 6) final projection -> d_out
    gemm_out<<<dim3(1024 / 128, 2048 / 128), blk, GEMM_SMEM>>>(b_o, out);
}